// round 1
// baseline (speedup 1.0000x reference)
#include <cuda_runtime.h>
#include <math.h>

// Problem constants
#define SQ    1024      // sequence length
#define DM    512       // model dim
#define NH    8         // heads
#define HDIM  64        // head dim
#define NLAY  4         // layers
#define QK_SCALE 0.125f // 1/sqrt(64)

// ---------------------------------------------------------------------------
// Scratch (no allocations allowed -> __device__ globals)
// ---------------------------------------------------------------------------
__device__ float g_h [SQ*DM];
__device__ float g_n [SQ*DM];
__device__ float g_q [SQ*DM];
__device__ float g_k [SQ*DM];
__device__ float g_v [SQ*DM];
__device__ float g_ao[SQ*DM];
__device__ float g_f1[SQ*2048];
__device__ float g_fi[SQ*1024];
__device__ float g_sc[(size_t)NH*SQ*SQ];   // 32 MB attention scores

__device__ __forceinline__ float gelu_f(float x){
    return 0.5f*x*(1.f + erff(x*0.7071067811865476f));
}

// ---------------------------------------------------------------------------
// Generic tiled fp32 GEMM: C[z] = A[z] @ B[z] (+bias) (+gelu | +residual)
// BM=BN=64, BK=16, 256 threads, 4x4 per thread.
// EPI: 0 = bias, 1 = bias+gelu, 2 = bias+residual-add
// ---------------------------------------------------------------------------
template<int EPI>
__global__ __launch_bounds__(256) void gemm_k(
    const float* __restrict__ A, int lda, long sA,
    const float* __restrict__ B, int ldb, long sB,
    float* __restrict__ C, int ldc, long sC,
    const float* __restrict__ bias,
    const float* __restrict__ res,
    int M, int N, int K)
{
    __shared__ float As[16][68];
    __shared__ float Bs[16][68];

    const int z = blockIdx.z;
    A += (long)z*sA; B += (long)z*sB; C += (long)z*sC;
    if (EPI == 2) res += (long)z*sC;

    const int tid = threadIdx.x;
    const int tx = tid & 15, ty = tid >> 4;
    const int row0 = blockIdx.y*64, col0 = blockIdx.x*64;

    float acc[4][4] = {};

    for (int k0 = 0; k0 < K; k0 += 16) {
        // load A tile 64x16 (coalesced on K), store transposed As[k][m]
        #pragma unroll
        for (int i = 0; i < 4; i++){
            int idx = tid + i*256;
            int r = idx >> 4, c = idx & 15;
            As[c][r] = A[(long)(row0+r)*lda + (k0+c)];
        }
        // load B tile 16x64 (coalesced on N)
        #pragma unroll
        for (int i = 0; i < 4; i++){
            int idx = tid + i*256;
            int r = idx >> 6, c = idx & 63;
            int col = col0 + c;
            Bs[r][c] = (col < N) ? B[(long)(k0+r)*ldb + col] : 0.f;
        }
        __syncthreads();
        #pragma unroll
        for (int kk = 0; kk < 16; kk++){
            float4 a4 = *(const float4*)&As[kk][ty*4];
            float4 b4 = *(const float4*)&Bs[kk][tx*4];
            float a[4] = {a4.x, a4.y, a4.z, a4.w};
            float b[4] = {b4.x, b4.y, b4.z, b4.w};
            #pragma unroll
            for (int i = 0; i < 4; i++)
                #pragma unroll
                for (int j = 0; j < 4; j++)
                    acc[i][j] = fmaf(a[i], b[j], acc[i][j]);
        }
        __syncthreads();
    }

    #pragma unroll
    for (int i = 0; i < 4; i++){
        int r = row0 + ty*4 + i;
        if (r >= M) continue;
        #pragma unroll
        for (int j = 0; j < 4; j++){
            int col = col0 + tx*4 + j;
            if (col < N){
                float v = acc[i][j];
                if (bias) v += bias[col];
                if (EPI == 1) v = gelu_f(v);
                if (EPI == 2) v += res[(long)r*ldc + col];
                C[(long)r*ldc + col] = v;
            }
        }
    }
}

// ---------------------------------------------------------------------------
// LayerNorm over D=512. One block (128 threads, 1 float4 each) per row.
// ---------------------------------------------------------------------------
__global__ __launch_bounds__(128) void ln_k(
    const float* __restrict__ x, const float* __restrict__ g,
    const float* __restrict__ b, float* __restrict__ y)
{
    const int row = blockIdx.x, tid = threadIdx.x;
    float4 v = reinterpret_cast<const float4*>(x + (long)row*DM)[tid];
    float s  = v.x+v.y+v.z+v.w;
    float s2 = v.x*v.x+v.y*v.y+v.z*v.z+v.w*v.w;
    #pragma unroll
    for (int o = 16; o; o >>= 1){
        s  += __shfl_xor_sync(0xffffffffu, s,  o);
        s2 += __shfl_xor_sync(0xffffffffu, s2, o);
    }
    __shared__ float sh[8];
    if ((tid & 31) == 0){ sh[tid>>5] = s; sh[4 + (tid>>5)] = s2; }
    __syncthreads();
    s  = sh[0]+sh[1]+sh[2]+sh[3];
    s2 = sh[4]+sh[5]+sh[6]+sh[7];
    const float m = s * (1.f/DM);
    const float rstd = rsqrtf(s2*(1.f/DM) - m*m + 1e-5f);
    float4 gg = reinterpret_cast<const float4*>(g)[tid];
    float4 bb = reinterpret_cast<const float4*>(b)[tid];
    float4 o;
    o.x = (v.x-m)*rstd*gg.x + bb.x;
    o.y = (v.y-m)*rstd*gg.y + bb.y;
    o.z = (v.z-m)*rstd*gg.z + bb.z;
    o.w = (v.w-m)*rstd*gg.w + bb.w;
    reinterpret_cast<float4*>(y + (long)row*DM)[tid] = o;
}

// ---------------------------------------------------------------------------
// Fused attention scores: sc[h][s][t] = scale*q_h[s].k_h[t] + q_h[s].Er[s-t+1023]
// 32x32 tile per block; Er band of 63 diagonals in shared.
// ---------------------------------------------------------------------------
__global__ __launch_bounds__(256) void scores_k(
    const float* __restrict__ q, const float* __restrict__ k,
    const float* __restrict__ Erl, float* __restrict__ sc)
{
    __shared__ float qs[32][65];
    __shared__ float ks[32][65];
    __shared__ float es[63][65];

    const int h  = blockIdx.z;
    const int s0 = blockIdx.y*32, t0 = blockIdx.x*32;
    const int tid = threadIdx.x;

    #pragma unroll
    for (int i = 0; i < 8; i++){
        int idx = tid + i*256;              // 0..2047
        int r = idx >> 6, d = idx & 63;
        qs[r][d] = q[(long)(s0+r)*DM + h*HDIM + d];
        ks[r][d] = k[(long)(t0+r)*DM + h*HDIM + d];
    }
    // Er rows needed: r = (s-t)+1023 for s in [s0,s0+32), t in [t0,t0+32)
    const int rbase = s0 - t0 + 992;        // = (s0-t0) + 1023 - 31, in [0,1984]
    #pragma unroll
    for (int i = 0; i < 16; i++){
        int idx = tid + i*256;
        if (idx < 63*64){
            int r = idx >> 6, d = idx & 63;
            es[r][d] = Erl[(long)(rbase+r)*HDIM + d];
        }
    }
    __syncthreads();

    const int tx = tid & 15, ty = tid >> 4;
    const int s_ = ty*2, t_ = tx*2;
    const int rb = s_ - t_ + 31;            // in [1,61]

    float a00=0.f, a01=0.f, a10=0.f, a11=0.f;
    #pragma unroll 8
    for (int d = 0; d < 64; d++){
        float q0 = qs[s_  ][d];
        float q1 = qs[s_+1][d];
        float sk0 = QK_SCALE * ks[t_  ][d];
        float sk1 = QK_SCALE * ks[t_+1][d];
        float em = es[rb-1][d];
        float e0 = es[rb  ][d];
        float ep = es[rb+1][d];
        a00 = fmaf(q0, sk0 + e0, a00);
        a01 = fmaf(q0, sk1 + em, a01);
        a10 = fmaf(q1, sk0 + ep, a10);
        a11 = fmaf(q1, sk1 + e0, a11);
    }
    float* out = sc + (long)h*SQ*SQ;
    out[(long)(s0+s_  )*SQ + (t0+t_  )] = a00;
    out[(long)(s0+s_  )*SQ + (t0+t_+1)] = a01;
    out[(long)(s0+s_+1)*SQ + (t0+t_  )] = a10;
    out[(long)(s0+s_+1)*SQ + (t0+t_+1)] = a11;
}

// ---------------------------------------------------------------------------
// Row softmax over 1024 cols. One block (256 threads, 1 float4 each) per row.
// ---------------------------------------------------------------------------
__global__ __launch_bounds__(256) void softmax_k(float* __restrict__ sc)
{
    const long row = blockIdx.x;
    float4* p = reinterpret_cast<float4*>(sc + row*(long)SQ);
    const int tid = threadIdx.x;
    float4 v = p[tid];
    float mx = fmaxf(fmaxf(v.x,v.y), fmaxf(v.z,v.w));
    #pragma unroll
    for (int o = 16; o; o >>= 1) mx = fmaxf(mx, __shfl_xor_sync(0xffffffffu, mx, o));
    __shared__ float sh[8];
    if ((tid & 31) == 0) sh[tid>>5] = mx;
    __syncthreads();
    mx = fmaxf(fmaxf(fmaxf(sh[0],sh[1]), fmaxf(sh[2],sh[3])),
               fmaxf(fmaxf(sh[4],sh[5]), fmaxf(sh[6],sh[7])));
    __syncthreads();
    v.x = expf(v.x - mx); v.y = expf(v.y - mx);
    v.z = expf(v.z - mx); v.w = expf(v.w - mx);
    float s = v.x+v.y+v.z+v.w;
    #pragma unroll
    for (int o = 16; o; o >>= 1) s += __shfl_xor_sync(0xffffffffu, s, o);
    if ((tid & 31) == 0) sh[tid>>5] = s;
    __syncthreads();
    s = sh[0]+sh[1]+sh[2]+sh[3]+sh[4]+sh[5]+sh[6]+sh[7];
    const float inv = 1.f/s;
    v.x *= inv; v.y *= inv; v.z *= inv; v.w *= inv;
    p[tid] = v;
}

// ---------------------------------------------------------------------------
// Host orchestration
// ---------------------------------------------------------------------------
extern "C" void kernel_launch(void* const* d_in, const int* in_sizes, int n_in,
                              void* d_out, int out_size)
{
    const float* x     = (const float*)d_in[0];   // (1,1024,128)
    const float* emb_W = (const float*)d_in[1];   // (128,512)
    const float* emb_b = (const float*)d_in[2];   // (512)
    const float* Wq    = (const float*)d_in[3];   // (4,512,512)
    const float* bq    = (const float*)d_in[4];   // (4,512)
    const float* Wk    = (const float*)d_in[5];
    const float* bk    = (const float*)d_in[6];
    const float* Wv    = (const float*)d_in[7];
    const float* bv    = (const float*)d_in[8];
    const float* Wo    = (const float*)d_in[9];
    const float* bo    = (const float*)d_in[10];
    const float* Er    = (const float*)d_in[11];  // (4,2047,64)
    const float* ln1g  = (const float*)d_in[12];
    const float* ln1b  = (const float*)d_in[13];
    const float* W1    = (const float*)d_in[14];  // (4,512,2048)
    const float* b1    = (const float*)d_in[15];
    const float* W2    = (const float*)d_in[16];  // (4,2048,512)
    const float* b2    = (const float*)d_in[17];
    const float* ln2g  = (const float*)d_in[18];
    const float* ln2b  = (const float*)d_in[19];
    const float* lnfg  = (const float*)d_in[20];
    const float* lnfb  = (const float*)d_in[21];
    const float* Wi    = (const float*)d_in[22];  // (512,1024)
    const float* bi    = (const float*)d_in[23];
    const float* Wf    = (const float*)d_in[24];  // (1024,390)
    const float* bf    = (const float*)d_in[25];
    float* out = (float*)d_out;

    float *h, *n, *q, *k, *v, *ao, *f1, *fi, *sc;
    cudaGetSymbolAddress((void**)&h,  g_h);
    cudaGetSymbolAddress((void**)&n,  g_n);
    cudaGetSymbolAddress((void**)&q,  g_q);
    cudaGetSymbolAddress((void**)&k,  g_k);
    cudaGetSymbolAddress((void**)&v,  g_v);
    cudaGetSymbolAddress((void**)&ao, g_ao);
    cudaGetSymbolAddress((void**)&f1, g_f1);
    cudaGetSymbolAddress((void**)&fi, g_fi);
    cudaGetSymbolAddress((void**)&sc, g_sc);

    // embed: h = x @ emb_W + emb_b   (1024x128 @ 128x512)
    gemm_k<0><<<dim3(8,16,1), 256>>>(x,128,0, emb_W,512,0, h,512,0,
                                     emb_b, nullptr, SQ, DM, 128);

    for (int l = 0; l < NLAY; l++) {
        const float* Wq_l = Wq + (long)l*DM*DM;
        const float* Wk_l = Wk + (long)l*DM*DM;
        const float* Wv_l = Wv + (long)l*DM*DM;
        const float* Wo_l = Wo + (long)l*DM*DM;
        const float* Er_l = Er + (long)l*2047*HDIM;
        const float* W1_l = W1 + (long)l*DM*2048;
        const float* W2_l = W2 + (long)l*2048*DM;

        // n = LN1(h)
        ln_k<<<SQ,128>>>(h, ln1g + l*DM, ln1b + l*DM, n);

        // q,k,v = n @ W + b  (each 1024x512 @ 512x512)
        gemm_k<0><<<dim3(8,16,1),256>>>(n,DM,0, Wq_l,DM,0, q,DM,0, bq + l*DM, nullptr, SQ, DM, DM);
        gemm_k<0><<<dim3(8,16,1),256>>>(n,DM,0, Wk_l,DM,0, k,DM,0, bk + l*DM, nullptr, SQ, DM, DM);
        gemm_k<0><<<dim3(8,16,1),256>>>(n,DM,0, Wv_l,DM,0, v,DM,0, bv + l*DM, nullptr, SQ, DM, DM);

        // scores (+rel), then softmax
        scores_k<<<dim3(32,32,NH),256>>>(q, k, Er_l, sc);
        softmax_k<<<NH*SQ,256>>>(sc);

        // ao[s, h*64+d] = attn_h @ v_h   (per head: 1024x1024 @ 1024x64)
        gemm_k<0><<<dim3(1,16,NH),256>>>(sc,SQ,(long)SQ*SQ, v,DM,HDIM, ao,DM,HDIM,
                                         nullptr, nullptr, SQ, HDIM, SQ);

        // h = h + ao @ Wo + bo
        gemm_k<2><<<dim3(8,16,1),256>>>(ao,DM,0, Wo_l,DM,0, h,DM,0, bo + l*DM, h, SQ, DM, DM);

        // n = LN2(h)
        ln_k<<<SQ,128>>>(h, ln2g + l*DM, ln2b + l*DM, n);

        // f1 = gelu(n @ W1 + b1)   (1024x512 @ 512x2048)
        gemm_k<1><<<dim3(32,16,1),256>>>(n,DM,0, W1_l,2048,0, f1,2048,0, b1 + l*2048, nullptr, SQ, 2048, DM);

        // h = h + f1 @ W2 + b2   (1024x2048 @ 2048x512)
        gemm_k<2><<<dim3(8,16,1),256>>>(f1,2048,0, W2_l,DM,0, h,DM,0, b2 + l*DM, h, SQ, DM, 2048);
    }

    // final: n = LNf(h); fi = gelu(n @ Wi + bi); out = fi @ Wf + bf
    ln_k<<<SQ,128>>>(h, lnfg, lnfb, n);
    gemm_k<1><<<dim3(16,16,1),256>>>(n,DM,0, Wi,1024,0, fi,1024,0, bi, nullptr, SQ, 1024, DM);
    gemm_k<0><<<dim3(7,16,1),256>>>(fi,1024,0, Wf,390,0, out,390,0, bf, nullptr, SQ, 390, 1024);
}

// round 4
// speedup vs baseline: 1.2516x; 1.2516x over previous
#include <cuda_runtime.h>
#include <math.h>
#include <stdint.h>

// Problem constants
#define SQ    1024      // sequence length
#define DM    512       // model dim
#define NH    8         // heads
#define HDIM  64        // head dim
#define NLAY  4         // layers
#define QK_SCALE 0.125f // 1/sqrt(64)

// ---------------------------------------------------------------------------
// Scratch (no allocations allowed -> __device__ globals)
// ---------------------------------------------------------------------------
__device__ float g_h [SQ*DM];
__device__ float g_n [SQ*DM];
__device__ float g_q [SQ*DM];
__device__ float g_k [SQ*DM];
__device__ float g_v [SQ*DM];
__device__ float g_ao[SQ*DM];
__device__ float g_f1[SQ*2048];
__device__ float g_fi[SQ*1024];
__device__ float g_sc[(size_t)NH*SQ*SQ];   // 32 MB attention scores

__device__ __forceinline__ float gelu_f(float x){
    return 0.5f*x*(1.f + erff(x*0.7071067811865476f));
}

__device__ __forceinline__ uint32_t f2tf(float x){
    uint32_t u; asm("cvt.rna.tf32.f32 %0, %1;" : "=r"(u) : "f"(x)); return u;
}

__device__ __forceinline__ void mma_tf32(float c[4],
    uint32_t a0, uint32_t a1, uint32_t a2, uint32_t a3,
    uint32_t b0, uint32_t b1)
{
    asm volatile(
        "mma.sync.aligned.m16n8k8.row.col.f32.tf32.tf32.f32 "
        "{%0,%1,%2,%3}, {%4,%5,%6,%7}, {%8,%9}, {%0,%1,%2,%3};"
        : "+f"(c[0]), "+f"(c[1]), "+f"(c[2]), "+f"(c[3])
        : "r"(a0), "r"(a1), "r"(a2), "r"(a3), "r"(b0), "r"(b1));
}

// ---------------------------------------------------------------------------
// 3xTF32 tensor-core GEMM: C[z] = A[z] @ B[z] (+bias) (+gelu | +residual)
// Block tile 64x64, BK=16, 256 threads = 8 warps (4x2), warp tile 16x32.
// Error-compensated: A,B split into tf32 hi+lo; acc += Ah*Bh + Ah*Bl + Al*Bh
// -> ~fp32 accuracy at tensor-core speed.
// EPI: 0 = bias, 1 = bias+gelu, 2 = bias+residual-add
// ---------------------------------------------------------------------------
template<int EPI>
__global__ __launch_bounds__(256) void gemm_tc(
    const float* __restrict__ A, int lda, long sA,
    const float* __restrict__ B, int ldb, long sB,
    float* __restrict__ C, int ldc, long sC,
    const float* __restrict__ bias,
    const float* __restrict__ res,
    int M, int N, int K)
{
    // padded, bank-conflict-free layouts (A stride 20, B stride 72)
    __shared__ uint32_t Ah[64][20];
    __shared__ uint32_t Al[64][20];
    __shared__ uint32_t Bh[16][72];
    __shared__ uint32_t Bl[16][72];

    const int z = blockIdx.z;
    A += (long)z*sA; B += (long)z*sB; C += (long)z*sC;
    if (EPI == 2) res += (long)z*sC;

    const int tid  = threadIdx.x;
    const int lane = tid & 31;
    const int w    = tid >> 5;
    const int wm   = w & 3;           // warp row group (0..3) -> 16 rows each
    const int wn   = w >> 2;          // warp col group (0..1) -> 32 cols each
    const int g    = lane >> 2;       // group id (0..7)
    const int t    = lane & 3;        // thread-in-group (0..3)

    const int row0 = blockIdx.y*64, col0 = blockIdx.x*64;

    float acc[4][4] = {};

    // A-load mapping: each thread loads one float4 (64 rows x 4 quads)
    const int ar  = tid >> 2;
    const int ac4 = (tid & 3) * 4;

    for (int k0 = 0; k0 < K; k0 += 16) {
        // ---- A tile: 64x16, float4 coalesced along K, split into hi/lo
        {
            float4 av = *(const float4*)(A + (long)(row0+ar)*lda + (k0+ac4));
            float vv[4] = {av.x, av.y, av.z, av.w};
            #pragma unroll
            for (int j = 0; j < 4; j++){
                uint32_t hi = f2tf(vv[j]);
                Ah[ar][ac4+j] = hi;
                Al[ar][ac4+j] = f2tf(vv[j] - __uint_as_float(hi));
            }
        }
        // ---- B tile: 16x64, scalar coalesced along N (handles any ldb/N)
        #pragma unroll
        for (int j = 0; j < 4; j++){
            int idx = tid + j*256;
            int br = idx >> 6, bc = idx & 63;
            int col = col0 + bc;
            float v = (col < N) ? B[(long)(k0+br)*ldb + col] : 0.f;
            uint32_t hi = f2tf(v);
            Bh[br][bc] = hi;
            Bl[br][bc] = f2tf(v - __uint_as_float(hi));
        }
        __syncthreads();

        #pragma unroll
        for (int ks = 0; ks < 16; ks += 8){
            // A fragments (m16 x k8), rows wm*16 + g (+8), cols ks + t (+4)
            uint32_t ah0 = Ah[wm*16 + g    ][ks + t    ];
            uint32_t ah1 = Ah[wm*16 + g + 8][ks + t    ];
            uint32_t ah2 = Ah[wm*16 + g    ][ks + t + 4];
            uint32_t ah3 = Ah[wm*16 + g + 8][ks + t + 4];
            uint32_t al0 = Al[wm*16 + g    ][ks + t    ];
            uint32_t al1 = Al[wm*16 + g + 8][ks + t    ];
            uint32_t al2 = Al[wm*16 + g    ][ks + t + 4];
            uint32_t al3 = Al[wm*16 + g + 8][ks + t + 4];
            #pragma unroll
            for (int nt = 0; nt < 4; nt++){
                int bn = wn*32 + nt*8 + g;
                uint32_t bh0 = Bh[ks + t    ][bn];
                uint32_t bh1 = Bh[ks + t + 4][bn];
                uint32_t bl0 = Bl[ks + t    ][bn];
                uint32_t bl1 = Bl[ks + t + 4][bn];
                mma_tf32(acc[nt], ah0, ah1, ah2, ah3, bh0, bh1);
                mma_tf32(acc[nt], ah0, ah1, ah2, ah3, bl0, bl1);
                mma_tf32(acc[nt], al0, al1, al2, al3, bh0, bh1);
            }
        }
        __syncthreads();
    }

    // ---- epilogue: c0:(g,2t) c1:(g,2t+1) c2:(g+8,2t) c3:(g+8,2t+1)
    const int r0 = row0 + wm*16 + g;
    const int r1 = r0 + 8;
    #pragma unroll
    for (int nt = 0; nt < 4; nt++){
        int col = col0 + wn*32 + nt*8 + 2*t;
        #pragma unroll
        for (int j = 0; j < 2; j++){
            int c = col + j;
            if (c < N){
                float v0 = acc[nt][j];       // row r0
                float v1 = acc[nt][2+j];     // row r1
                if (bias){ float bb = bias[c]; v0 += bb; v1 += bb; }
                if (EPI == 1){ v0 = gelu_f(v0); v1 = gelu_f(v1); }
                if (EPI == 2){
                    v0 += res[(long)r0*ldc + c];
                    v1 += res[(long)r1*ldc + c];
                }
                C[(long)r0*ldc + c] = v0;
                C[(long)r1*ldc + c] = v1;
            }
        }
    }
}

// ---------------------------------------------------------------------------
// LayerNorm over D=512. One block (128 threads, 1 float4 each) per row.
// ---------------------------------------------------------------------------
__global__ __launch_bounds__(128) void ln_k(
    const float* __restrict__ x, const float* __restrict__ g,
    const float* __restrict__ b, float* __restrict__ y)
{
    const int row = blockIdx.x, tid = threadIdx.x;
    float4 v = reinterpret_cast<const float4*>(x + (long)row*DM)[tid];
    float s  = v.x+v.y+v.z+v.w;
    float s2 = v.x*v.x+v.y*v.y+v.z*v.z+v.w*v.w;
    #pragma unroll
    for (int o = 16; o; o >>= 1){
        s  += __shfl_xor_sync(0xffffffffu, s,  o);
        s2 += __shfl_xor_sync(0xffffffffu, s2, o);
    }
    __shared__ float sh[8];
    if ((tid & 31) == 0){ sh[tid>>5] = s; sh[4 + (tid>>5)] = s2; }
    __syncthreads();
    s  = sh[0]+sh[1]+sh[2]+sh[3];
    s2 = sh[4]+sh[5]+sh[6]+sh[7];
    const float m = s * (1.f/DM);
    const float rstd = rsqrtf(s2*(1.f/DM) - m*m + 1e-5f);
    float4 gg = reinterpret_cast<const float4*>(g)[tid];
    float4 bb = reinterpret_cast<const float4*>(b)[tid];
    float4 o;
    o.x = (v.x-m)*rstd*gg.x + bb.x;
    o.y = (v.y-m)*rstd*gg.y + bb.y;
    o.z = (v.z-m)*rstd*gg.z + bb.z;
    o.w = (v.w-m)*rstd*gg.w + bb.w;
    reinterpret_cast<float4*>(y + (long)row*DM)[tid] = o;
}

// ---------------------------------------------------------------------------
// Fused attention scores: sc[h][s][t] = scale*q_h[s].k_h[t] + q_h[s].Er[s-t+1023]
// 32x32 tile per block; Er band of 63 diagonals in shared. Exact fp32 (keeps
// softmax inputs accurate).
// ---------------------------------------------------------------------------
__global__ __launch_bounds__(256) void scores_k(
    const float* __restrict__ q, const float* __restrict__ k,
    const float* __restrict__ Erl, float* __restrict__ sc)
{
    __shared__ float qs[32][65];
    __shared__ float ks[32][65];
    __shared__ float es[63][65];

    const int h  = blockIdx.z;
    const int s0 = blockIdx.y*32, t0 = blockIdx.x*32;
    const int tid = threadIdx.x;

    #pragma unroll
    for (int i = 0; i < 8; i++){
        int idx = tid + i*256;              // 0..2047
        int r = idx >> 6, d = idx & 63;
        qs[r][d] = q[(long)(s0+r)*DM + h*HDIM + d];
        ks[r][d] = k[(long)(t0+r)*DM + h*HDIM + d];
    }
    const int rbase = s0 - t0 + 992;
    #pragma unroll
    for (int i = 0; i < 16; i++){
        int idx = tid + i*256;
        if (idx < 63*64){
            int r = idx >> 6, d = idx & 63;
            es[r][d] = Erl[(long)(rbase+r)*HDIM + d];
        }
    }
    __syncthreads();

    const int tx = tid & 15, ty = tid >> 4;
    const int s_ = ty*2, t_ = tx*2;
    const int rb = s_ - t_ + 31;

    float a00=0.f, a01=0.f, a10=0.f, a11=0.f;
    #pragma unroll 8
    for (int d = 0; d < 64; d++){
        float q0 = qs[s_  ][d];
        float q1 = qs[s_+1][d];
        float sk0 = QK_SCALE * ks[t_  ][d];
        float sk1 = QK_SCALE * ks[t_+1][d];
        float em = es[rb-1][d];
        float e0 = es[rb  ][d];
        float ep = es[rb+1][d];
        a00 = fmaf(q0, sk0 + e0, a00);
        a01 = fmaf(q0, sk1 + em, a01);
        a10 = fmaf(q1, sk0 + ep, a10);
        a11 = fmaf(q1, sk1 + e0, a11);
    }
    float* out = sc + (long)h*SQ*SQ;
    out[(long)(s0+s_  )*SQ + (t0+t_  )] = a00;
    out[(long)(s0+s_  )*SQ + (t0+t_+1)] = a01;
    out[(long)(s0+s_+1)*SQ + (t0+t_  )] = a10;
    out[(long)(s0+s_+1)*SQ + (t0+t_+1)] = a11;
}

// ---------------------------------------------------------------------------
// Row softmax over 1024 cols. One block (256 threads, 1 float4 each) per row.
// ---------------------------------------------------------------------------
__global__ __launch_bounds__(256) void softmax_k(float* __restrict__ sc)
{
    const long row = blockIdx.x;
    float4* p = reinterpret_cast<float4*>(sc + row*(long)SQ);
    const int tid = threadIdx.x;
    float4 v = p[tid];
    float mx = fmaxf(fmaxf(v.x,v.y), fmaxf(v.z,v.w));
    #pragma unroll
    for (int o = 16; o; o >>= 1) mx = fmaxf(mx, __shfl_xor_sync(0xffffffffu, mx, o));
    __shared__ float sh[8];
    if ((tid & 31) == 0) sh[tid>>5] = mx;
    __syncthreads();
    mx = fmaxf(fmaxf(fmaxf(sh[0],sh[1]), fmaxf(sh[2],sh[3])),
               fmaxf(fmaxf(sh[4],sh[5]), fmaxf(sh[6],sh[7])));
    __syncthreads();
    v.x = expf(v.x - mx); v.y = expf(v.y - mx);
    v.z = expf(v.z - mx); v.w = expf(v.w - mx);
    float s = v.x+v.y+v.z+v.w;
    #pragma unroll
    for (int o = 16; o; o >>= 1) s += __shfl_xor_sync(0xffffffffu, s, o);
    if ((tid & 31) == 0) sh[tid>>5] = s;
    __syncthreads();
    s = sh[0]+sh[1]+sh[2]+sh[3]+sh[4]+sh[5]+sh[6]+sh[7];
    const float inv = 1.f/s;
    v.x *= inv; v.y *= inv; v.z *= inv; v.w *= inv;
    p[tid] = v;
}

// ---------------------------------------------------------------------------
// Host orchestration
// ---------------------------------------------------------------------------
extern "C" void kernel_launch(void* const* d_in, const int* in_sizes, int n_in,
                              void* d_out, int out_size)
{
    const float* x     = (const float*)d_in[0];   // (1,1024,128)
    const float* emb_W = (const float*)d_in[1];   // (128,512)
    const float* emb_b = (const float*)d_in[2];   // (512)
    const float* Wq    = (const float*)d_in[3];   // (4,512,512)
    const float* bq    = (const float*)d_in[4];   // (4,512)
    const float* Wk    = (const float*)d_in[5];
    const float* bk    = (const float*)d_in[6];
    const float* Wv    = (const float*)d_in[7];
    const float* bv    = (const float*)d_in[8];
    const float* Wo    = (const float*)d_in[9];
    const float* bo    = (const float*)d_in[10];
    const float* Er    = (const float*)d_in[11];  // (4,2047,64)
    const float* ln1g  = (const float*)d_in[12];
    const float* ln1b  = (const float*)d_in[13];
    const float* W1    = (const float*)d_in[14];  // (4,512,2048)
    const float* b1    = (const float*)d_in[15];
    const float* W2    = (const float*)d_in[16];  // (4,2048,512)
    const float* b2    = (const float*)d_in[17];
    const float* ln2g  = (const float*)d_in[18];
    const float* ln2b  = (const float*)d_in[19];
    const float* lnfg  = (const float*)d_in[20];
    const float* lnfb  = (const float*)d_in[21];
    const float* Wi    = (const float*)d_in[22];  // (512,1024)
    const float* bi    = (const float*)d_in[23];
    const float* Wf    = (const float*)d_in[24];  // (1024,390)
    const float* bf    = (const float*)d_in[25];
    float* out = (float*)d_out;

    float *h, *n, *q, *k, *v, *ao, *f1, *fi, *sc;
    cudaGetSymbolAddress((void**)&h,  g_h);
    cudaGetSymbolAddress((void**)&n,  g_n);
    cudaGetSymbolAddress((void**)&q,  g_q);
    cudaGetSymbolAddress((void**)&k,  g_k);
    cudaGetSymbolAddress((void**)&v,  g_v);
    cudaGetSymbolAddress((void**)&ao, g_ao);
    cudaGetSymbolAddress((void**)&f1, g_f1);
    cudaGetSymbolAddress((void**)&fi, g_fi);
    cudaGetSymbolAddress((void**)&sc, g_sc);

    // embed: h = x @ emb_W + emb_b   (1024x128 @ 128x512)
    gemm_tc<0><<<dim3(8,16,1), 256>>>(x,128,0, emb_W,512,0, h,512,0,
                                      emb_b, nullptr, SQ, DM, 128);

    for (int l = 0; l < NLAY; l++) {
        const float* Wq_l = Wq + (long)l*DM*DM;
        const float* Wk_l = Wk + (long)l*DM*DM;
        const float* Wv_l = Wv + (long)l*DM*DM;
        const float* Wo_l = Wo + (long)l*DM*DM;
        const float* Er_l = Er + (long)l*2047*HDIM;
        const float* W1_l = W1 + (long)l*DM*2048;
        const float* W2_l = W2 + (long)l*2048*DM;

        // n = LN1(h)
        ln_k<<<SQ,128>>>(h, ln1g + l*DM, ln1b + l*DM, n);

        // q,k,v = n @ W + b  (each 1024x512 @ 512x512)
        gemm_tc<0><<<dim3(8,16,1),256>>>(n,DM,0, Wq_l,DM,0, q,DM,0, bq + l*DM, nullptr, SQ, DM, DM);
        gemm_tc<0><<<dim3(8,16,1),256>>>(n,DM,0, Wk_l,DM,0, k,DM,0, bk + l*DM, nullptr, SQ, DM, DM);
        gemm_tc<0><<<dim3(8,16,1),256>>>(n,DM,0, Wv_l,DM,0, v,DM,0, bv + l*DM, nullptr, SQ, DM, DM);

        // scores (+rel), then softmax
        scores_k<<<dim3(32,32,NH),256>>>(q, k, Er_l, sc);
        softmax_k<<<NH*SQ,256>>>(sc);

        // ao[s, h*64+d] = attn_h @ v_h   (per head: 1024x1024 @ 1024x64)
        gemm_tc<0><<<dim3(1,16,NH),256>>>(sc,SQ,(long)SQ*SQ, v,DM,HDIM, ao,DM,HDIM,
                                          nullptr, nullptr, SQ, HDIM, SQ);

        // h = h + ao @ Wo + bo
        gemm_tc<2><<<dim3(8,16,1),256>>>(ao,DM,0, Wo_l,DM,0, h,DM,0, bo + l*DM, h, SQ, DM, DM);

        // n = LN2(h)
        ln_k<<<SQ,128>>>(h, ln2g + l*DM, ln2b + l*DM, n);

        // f1 = gelu(n @ W1 + b1)   (1024x512 @ 512x2048)
        gemm_tc<1><<<dim3(32,16,1),256>>>(n,DM,0, W1_l,2048,0, f1,2048,0, b1 + l*2048, nullptr, SQ, 2048, DM);

        // h = h + f1 @ W2 + b2   (1024x2048 @ 2048x512)
        gemm_tc<2><<<dim3(8,16,1),256>>>(f1,2048,0, W2_l,DM,0, h,DM,0, b2 + l*DM, h, SQ, DM, 2048);
    }

    // final: n = LNf(h); fi = gelu(n @ Wi + bi); out = fi @ Wf + bf
    ln_k<<<SQ,128>>>(h, lnfg, lnfb, n);
    gemm_tc<1><<<dim3(16,16,1),256>>>(n,DM,0, Wi,1024,0, fi,1024,0, bi, nullptr, SQ, 1024, DM);
    gemm_tc<0><<<dim3(7,16,1),256>>>(fi,1024,0, Wf,390,0, out,390,0, bf, nullptr, SQ, 390, 1024);
}

// round 6
// speedup vs baseline: 1.7807x; 1.4228x over previous
#include <cuda_runtime.h>
#include <math.h>
#include <stdint.h>

// Problem constants
#define SQ    1024      // sequence length
#define DM    512       // model dim
#define NH    8         // heads
#define HDIM  64        // head dim
#define NLAY  4         // layers
#define QK_SCALE 0.125f // 1/sqrt(64)

// ---------------------------------------------------------------------------
// Scratch (no allocations allowed -> __device__ globals)
// ---------------------------------------------------------------------------
__device__ float g_h [SQ*DM];
__device__ float g_n [SQ*DM];
__device__ float g_q [SQ*DM];
__device__ float g_k [SQ*DM];
__device__ float g_v [SQ*DM];
__device__ float g_ao[SQ*DM];
__device__ float g_f1[SQ*2048];
__device__ float g_fi[SQ*1024];
__device__ float g_sc[(size_t)NH*SQ*SQ];   // 32 MB attention scores

__device__ __forceinline__ float gelu_f(float x){
    return 0.5f*x*(1.f + erff(x*0.7071067811865476f));
}

__device__ __forceinline__ uint32_t f2tf(float x){
    uint32_t u; asm("cvt.rna.tf32.f32 %0, %1;" : "=r"(u) : "f"(x)); return u;
}

__device__ __forceinline__ void mma_tf32(float c[4],
    uint32_t a0, uint32_t a1, uint32_t a2, uint32_t a3,
    uint32_t b0, uint32_t b1)
{
    asm volatile(
        "mma.sync.aligned.m16n8k8.row.col.f32.tf32.tf32.f32 "
        "{%0,%1,%2,%3}, {%4,%5,%6,%7}, {%8,%9}, {%0,%1,%2,%3};"
        : "+f"(c[0]), "+f"(c[1]), "+f"(c[2]), "+f"(c[3])
        : "r"(a0), "r"(a1), "r"(a2), "r"(a3), "r"(b0), "r"(b1));
}

// ---------------------------------------------------------------------------
// 3xTF32 tensor-core GEMM core, register-double-buffered mainloop.
// Block tile 64x64, BK=16, 256 threads = 8 warps (4x2), warp tile 16x32.
// EPI: 0 = bias, 1 = bias+gelu, 2 = bias+residual-add
// ---------------------------------------------------------------------------
template<int EPI>
__device__ __forceinline__ void gemm_core(
    const float* __restrict__ A, int lda,
    const float* __restrict__ B, int ldb,
    float* __restrict__ C, int ldc,
    const float* __restrict__ bias,
    const float* __restrict__ res,
    int M, int N, int K, int row0, int col0)
{
    __shared__ uint32_t Ah[64][20];
    __shared__ uint32_t Al[64][20];
    __shared__ uint32_t Bh[16][72];
    __shared__ uint32_t Bl[16][72];

    const int tid  = threadIdx.x;
    const int lane = tid & 31;
    const int w    = tid >> 5;
    const int wm   = w & 3;
    const int wn   = w >> 2;
    const int g    = lane >> 2;
    const int t    = lane & 3;

    float acc[4][4] = {};

    // A-load mapping: one float4 per thread (64 rows x 4 quads)
    const int ar  = tid >> 2;
    const int ac4 = (tid & 3) * 4;
    // B-load mapping (vector): 16 rows x 16 float4 cols
    const int br  = tid >> 4;
    const int bc4 = (tid & 15) * 4;
    const bool vecB = ((ldb & 3) == 0) && (col0 + 64 <= N);

    float aR[4], bR[4];

    // prologue: load tile 0 into registers
    {
        float4 av = *(const float4*)(A + (long)(row0+ar)*lda + ac4);
        aR[0]=av.x; aR[1]=av.y; aR[2]=av.z; aR[3]=av.w;
        if (vecB){
            float4 bv = *(const float4*)(B + (long)br*ldb + col0 + bc4);
            bR[0]=bv.x; bR[1]=bv.y; bR[2]=bv.z; bR[3]=bv.w;
        } else {
            #pragma unroll
            for (int j = 0; j < 4; j++){
                int idx = tid + j*256;
                int r = idx >> 6, c = idx & 63;
                int col = col0 + c;
                bR[j] = (col < N) ? B[(long)r*ldb + col] : 0.f;
            }
        }
    }

    for (int k0 = 0; k0 < K; k0 += 16) {
        // store current tile (from regs) to smem, split hi/lo
        #pragma unroll
        for (int j = 0; j < 4; j++){
            uint32_t hi = f2tf(aR[j]);
            Ah[ar][ac4+j] = hi;
            Al[ar][ac4+j] = f2tf(aR[j] - __uint_as_float(hi));
        }
        if (vecB){
            #pragma unroll
            for (int j = 0; j < 4; j++){
                uint32_t hi = f2tf(bR[j]);
                Bh[br][bc4+j] = hi;
                Bl[br][bc4+j] = f2tf(bR[j] - __uint_as_float(hi));
            }
        } else {
            #pragma unroll
            for (int j = 0; j < 4; j++){
                int idx = tid + j*256;
                int r = idx >> 6, c = idx & 63;
                uint32_t hi = f2tf(bR[j]);
                Bh[r][c] = hi;
                Bl[r][c] = f2tf(bR[j] - __uint_as_float(hi));
            }
        }
        __syncthreads();

        // prefetch next tile into registers (overlaps with MMAs below)
        if (k0 + 16 < K){
            float4 av = *(const float4*)(A + (long)(row0+ar)*lda + (k0+16+ac4));
            aR[0]=av.x; aR[1]=av.y; aR[2]=av.z; aR[3]=av.w;
            if (vecB){
                float4 bv = *(const float4*)(B + (long)(k0+16+br)*ldb + col0 + bc4);
                bR[0]=bv.x; bR[1]=bv.y; bR[2]=bv.z; bR[3]=bv.w;
            } else {
                #pragma unroll
                for (int j = 0; j < 4; j++){
                    int idx = tid + j*256;
                    int r = idx >> 6, c = idx & 63;
                    int col = col0 + c;
                    bR[j] = (col < N) ? B[(long)(k0+16+r)*ldb + col] : 0.f;
                }
            }
        }

        #pragma unroll
        for (int ks = 0; ks < 16; ks += 8){
            uint32_t ah0 = Ah[wm*16 + g    ][ks + t    ];
            uint32_t ah1 = Ah[wm*16 + g + 8][ks + t    ];
            uint32_t ah2 = Ah[wm*16 + g    ][ks + t + 4];
            uint32_t ah3 = Ah[wm*16 + g + 8][ks + t + 4];
            uint32_t al0 = Al[wm*16 + g    ][ks + t    ];
            uint32_t al1 = Al[wm*16 + g + 8][ks + t    ];
            uint32_t al2 = Al[wm*16 + g    ][ks + t + 4];
            uint32_t al3 = Al[wm*16 + g + 8][ks + t + 4];
            #pragma unroll
            for (int nt = 0; nt < 4; nt++){
                int bn = wn*32 + nt*8 + g;
                uint32_t bh0 = Bh[ks + t    ][bn];
                uint32_t bh1 = Bh[ks + t + 4][bn];
                uint32_t bl0 = Bl[ks + t    ][bn];
                uint32_t bl1 = Bl[ks + t + 4][bn];
                mma_tf32(acc[nt], ah0, ah1, ah2, ah3, bh0, bh1);
                mma_tf32(acc[nt], ah0, ah1, ah2, ah3, bl0, bl1);
                mma_tf32(acc[nt], al0, al1, al2, al3, bh0, bh1);
            }
        }
        __syncthreads();
    }

    // epilogue: c0:(g,2t) c1:(g,2t+1) c2:(g+8,2t) c3:(g+8,2t+1)
    const int r0 = row0 + wm*16 + g;
    const int r1 = r0 + 8;
    #pragma unroll
    for (int nt = 0; nt < 4; nt++){
        int col = col0 + wn*32 + nt*8 + 2*t;
        #pragma unroll
        for (int j = 0; j < 2; j++){
            int c = col + j;
            if (c < N){
                float v0 = acc[nt][j];
                float v1 = acc[nt][2+j];
                if (bias){ float bb = bias[c]; v0 += bb; v1 += bb; }
                if (EPI == 1){ v0 = gelu_f(v0); v1 = gelu_f(v1); }
                if (EPI == 2){
                    v0 += res[(long)r0*ldc + c];
                    v1 += res[(long)r1*ldc + c];
                }
                C[(long)r0*ldc + c] = v0;
                C[(long)r1*ldc + c] = v1;
            }
        }
    }
}

template<int EPI>
__global__ __launch_bounds__(256) void gemm_tc(
    const float* __restrict__ A, int lda, long sA,
    const float* __restrict__ B, int ldb, long sB,
    float* __restrict__ C, int ldc, long sC,
    const float* __restrict__ bias,
    const float* __restrict__ res,
    int M, int N, int K)
{
    const int z = blockIdx.z;
    gemm_core<EPI>(A + (long)z*sA, lda, B + (long)z*sB, ldb, C + (long)z*sC, ldc,
                   bias, (EPI==2) ? (res + (long)z*sC) : res,
                   M, N, K, blockIdx.y*64, blockIdx.x*64);
}

// Fused QKV: z picks (W, b, out); grid (8,16,3) = 384 blocks
__global__ __launch_bounds__(256) void gemm_qkv(
    const float* __restrict__ n,
    const float* __restrict__ Wq, const float* __restrict__ Wk, const float* __restrict__ Wv,
    const float* __restrict__ bq, const float* __restrict__ bk, const float* __restrict__ bv,
    float* __restrict__ q, float* __restrict__ k, float* __restrict__ v)
{
    const int z = blockIdx.z;
    const float* B    = (z==0) ? Wq : (z==1) ? Wk : Wv;
    const float* bias = (z==0) ? bq : (z==1) ? bk : bv;
    float*       C    = (z==0) ? q  : (z==1) ? k  : v;
    gemm_core<0>(n, DM, B, DM, C, DM, bias, nullptr,
                 SQ, DM, DM, blockIdx.y*64, blockIdx.x*64);
}

// ---------------------------------------------------------------------------
// LayerNorm over D=512. One block (128 threads, 1 float4 each) per row.
// ---------------------------------------------------------------------------
__global__ __launch_bounds__(128) void ln_k(
    const float* __restrict__ x, const float* __restrict__ g,
    const float* __restrict__ b, float* __restrict__ y)
{
    const int row = blockIdx.x, tid = threadIdx.x;
    float4 v = reinterpret_cast<const float4*>(x + (long)row*DM)[tid];
    float s  = v.x+v.y+v.z+v.w;
    float s2 = v.x*v.x+v.y*v.y+v.z*v.z+v.w*v.w;
    #pragma unroll
    for (int o = 16; o; o >>= 1){
        s  += __shfl_xor_sync(0xffffffffu, s,  o);
        s2 += __shfl_xor_sync(0xffffffffu, s2, o);
    }
    __shared__ float sh[8];
    if ((tid & 31) == 0){ sh[tid>>5] = s; sh[4 + (tid>>5)] = s2; }
    __syncthreads();
    s  = sh[0]+sh[1]+sh[2]+sh[3];
    s2 = sh[4]+sh[5]+sh[6]+sh[7];
    const float m = s * (1.f/DM);
    const float rstd = rsqrtf(s2*(1.f/DM) - m*m + 1e-5f);
    float4 gg = reinterpret_cast<const float4*>(g)[tid];
    float4 bb = reinterpret_cast<const float4*>(b)[tid];
    float4 o;
    o.x = (v.x-m)*rstd*gg.x + bb.x;
    o.y = (v.y-m)*rstd*gg.y + bb.y;
    o.z = (v.z-m)*rstd*gg.z + bb.z;
    o.w = (v.w-m)*rstd*gg.w + bb.w;
    reinterpret_cast<float4*>(y + (long)row*DM)[tid] = o;
}

// ---------------------------------------------------------------------------
// Fused attention scores: sc[h][s][t] = q_h[s].(scale*k_h[t]) + q_h[s].Er[s-t+1023]
// 64x64 tile, 4x4 microtile, d-major transposed smem -> 4x LDS.128 per d.
// Dynamic smem: qsT[64][68] + ksT[64][68] + esT[64][132] = 68608 B.
// ---------------------------------------------------------------------------
#define SCORES_SMEM ((64*68*2 + 64*132)*4)

__global__ __launch_bounds__(256) void scores_k(
    const float* __restrict__ q, const float* __restrict__ k,
    const float* __restrict__ Erl, float* __restrict__ sc)
{
    extern __shared__ float sm[];
    float* qsT = sm;               // [64][68] : qsT[d][s]
    float* ksT = sm + 64*68;       // [64][68] : ksT[d][t], pre-scaled
    float* esT = sm + 2*64*68;     // [64][132]: esT[d][r], r in 0..126

    const int h  = blockIdx.z;
    const int s0 = blockIdx.y*64, t0 = blockIdx.x*64;
    const int tid = threadIdx.x;

    #pragma unroll
    for (int i = 0; i < 16; i++){
        int idx = tid + i*256;           // 0..4095
        int r = idx >> 6, d = idx & 63;
        qsT[d*68 + r] = q[(long)(s0+r)*DM + h*HDIM + d];
        ksT[d*68 + r] = QK_SCALE * k[(long)(t0+r)*DM + h*HDIM + d];
    }
    // Er rows needed: rbase + 0..126, rbase = (s0-t0) + 1023 - 63
    const int rbase = s0 - t0 + 960;
    #pragma unroll
    for (int i = 0; i < 32; i++){
        int idx = tid + i*256;
        if (idx < 127*64){
            int r = idx >> 6, d = idx & 63;
            esT[d*132 + r] = Erl[(long)(rbase+r)*HDIM + d];
        }
    }
    __syncthreads();

    const int tx = tid & 15, ty = tid >> 4;
    const int s_ = ty*4, t_ = tx*4;
    const int rb0 = s_ - t_ + 60;        // multiple of 4, in [0,120]

    float acc[4][4] = {};
    #pragma unroll 4
    for (int d = 0; d < 64; d++){
        float4 qv = *(const float4*)&qsT[d*68 + s_];
        float4 kv = *(const float4*)&ksT[d*68 + t_];
        float4 e0 = *(const float4*)&esT[d*132 + rb0];
        float4 e1 = *(const float4*)&esT[d*132 + rb0 + 4];
        float qq[4] = {qv.x,qv.y,qv.z,qv.w};
        float kk[4] = {kv.x,kv.y,kv.z,kv.w};
        float ee[8] = {e0.x,e0.y,e0.z,e0.w,e1.x,e1.y,e1.z,e1.w};
        #pragma unroll
        for (int i = 0; i < 4; i++)
            #pragma unroll
            for (int j = 0; j < 4; j++)
                acc[i][j] = fmaf(qq[i], kk[j] + ee[i-j+3], acc[i][j]);
    }

    float* out = sc + (long)h*SQ*SQ;
    #pragma unroll
    for (int i = 0; i < 4; i++){
        float4 o = make_float4(acc[i][0], acc[i][1], acc[i][2], acc[i][3]);
        *(float4*)&out[(long)(s0+s_+i)*SQ + (t0+t_)] = o;
    }
}

// ---------------------------------------------------------------------------
// Row softmax over 1024 cols. One block (256 threads, 1 float4 each) per row.
// ---------------------------------------------------------------------------
__global__ __launch_bounds__(256) void softmax_k(float* __restrict__ sc)
{
    const long row = blockIdx.x;
    float4* p = reinterpret_cast<float4*>(sc + row*(long)SQ);
    const int tid = threadIdx.x;
    float4 v = p[tid];
    float mx = fmaxf(fmaxf(v.x,v.y), fmaxf(v.z,v.w));
    #pragma unroll
    for (int o = 16; o; o >>= 1) mx = fmaxf(mx, __shfl_xor_sync(0xffffffffu, mx, o));
    __shared__ float sh[8];
    if ((tid & 31) == 0) sh[tid>>5] = mx;
    __syncthreads();
    mx = fmaxf(fmaxf(fmaxf(sh[0],sh[1]), fmaxf(sh[2],sh[3])),
               fmaxf(fmaxf(sh[4],sh[5]), fmaxf(sh[6],sh[7])));
    __syncthreads();
    v.x = expf(v.x - mx); v.y = expf(v.y - mx);
    v.z = expf(v.z - mx); v.w = expf(v.w - mx);
    float s = v.x+v.y+v.z+v.w;
    #pragma unroll
    for (int o = 16; o; o >>= 1) s += __shfl_xor_sync(0xffffffffu, s, o);
    if ((tid & 31) == 0) sh[tid>>5] = s;
    __syncthreads();
    s = sh[0]+sh[1]+sh[2]+sh[3]+sh[4]+sh[5]+sh[6]+sh[7];
    const float inv = 1.f/s;
    v.x *= inv; v.y *= inv; v.z *= inv; v.w *= inv;
    p[tid] = v;
}

// ---------------------------------------------------------------------------
// Host orchestration
// ---------------------------------------------------------------------------
extern "C" void kernel_launch(void* const* d_in, const int* in_sizes, int n_in,
                              void* d_out, int out_size)
{
    const float* x     = (const float*)d_in[0];
    const float* emb_W = (const float*)d_in[1];
    const float* emb_b = (const float*)d_in[2];
    const float* Wq    = (const float*)d_in[3];
    const float* bq    = (const float*)d_in[4];
    const float* Wk    = (const float*)d_in[5];
    const float* bk    = (const float*)d_in[6];
    const float* Wv    = (const float*)d_in[7];
    const float* bv    = (const float*)d_in[8];
    const float* Wo    = (const float*)d_in[9];
    const float* bo    = (const float*)d_in[10];
    const float* Er    = (const float*)d_in[11];
    const float* ln1g  = (const float*)d_in[12];
    const float* ln1b  = (const float*)d_in[13];
    const float* W1    = (const float*)d_in[14];
    const float* b1    = (const float*)d_in[15];
    const float* W2    = (const float*)d_in[16];
    const float* b2    = (const float*)d_in[17];
    const float* ln2g  = (const float*)d_in[18];
    const float* ln2b  = (const float*)d_in[19];
    const float* lnfg  = (const float*)d_in[20];
    const float* lnfb  = (const float*)d_in[21];
    const float* Wi    = (const float*)d_in[22];
    const float* bi    = (const float*)d_in[23];
    const float* Wf    = (const float*)d_in[24];
    const float* bf    = (const float*)d_in[25];
    float* out = (float*)d_out;

    float *h, *n, *q, *k, *v, *ao, *f1, *fi, *sc;
    cudaGetSymbolAddress((void**)&h,  g_h);
    cudaGetSymbolAddress((void**)&n,  g_n);
    cudaGetSymbolAddress((void**)&q,  g_q);
    cudaGetSymbolAddress((void**)&k,  g_k);
    cudaGetSymbolAddress((void**)&v,  g_v);
    cudaGetSymbolAddress((void**)&ao, g_ao);
    cudaGetSymbolAddress((void**)&f1, g_f1);
    cudaGetSymbolAddress((void**)&fi, g_fi);
    cudaGetSymbolAddress((void**)&sc, g_sc);

    cudaFuncSetAttribute(scores_k, cudaFuncAttributeMaxDynamicSharedMemorySize, SCORES_SMEM);

    // embed: h = x @ emb_W + emb_b
    gemm_tc<0><<<dim3(8,16,1), 256>>>(x,128,0, emb_W,512,0, h,512,0,
                                      emb_b, nullptr, SQ, DM, 128);

    for (int l = 0; l < NLAY; l++) {
        const float* Wq_l = Wq + (long)l*DM*DM;
        const float* Wk_l = Wk + (long)l*DM*DM;
        const float* Wv_l = Wv + (long)l*DM*DM;
        const float* Wo_l = Wo + (long)l*DM*DM;
        const float* Er_l = Er + (long)l*2047*HDIM;
        const float* W1_l = W1 + (long)l*DM*2048;
        const float* W2_l = W2 + (long)l*2048*DM;

        ln_k<<<SQ,128>>>(h, ln1g + l*DM, ln1b + l*DM, n);

        // fused q,k,v projection
        gemm_qkv<<<dim3(8,16,3),256>>>(n, Wq_l, Wk_l, Wv_l,
                                       bq + l*DM, bk + l*DM, bv + l*DM, q, k, v);

        scores_k<<<dim3(16,16,NH),256,SCORES_SMEM>>>(q, k, Er_l, sc);
        softmax_k<<<NH*SQ,256>>>(sc);

        // ao = attn @ v (per head)
        gemm_tc<0><<<dim3(1,16,NH),256>>>(sc,SQ,(long)SQ*SQ, v,DM,HDIM, ao,DM,HDIM,
                                          nullptr, nullptr, SQ, HDIM, SQ);

        // h = h + ao @ Wo + bo
        gemm_tc<2><<<dim3(8,16,1),256>>>(ao,DM,0, Wo_l,DM,0, h,DM,0, bo + l*DM, h, SQ, DM, DM);

        ln_k<<<SQ,128>>>(h, ln2g + l*DM, ln2b + l*DM, n);

        // f1 = gelu(n @ W1 + b1)
        gemm_tc<1><<<dim3(32,16,1),256>>>(n,DM,0, W1_l,2048,0, f1,2048,0, b1 + l*2048, nullptr, SQ, 2048, DM);

        // h = h + f1 @ W2 + b2
        gemm_tc<2><<<dim3(8,16,1),256>>>(f1,2048,0, W2_l,DM,0, h,DM,0, b2 + l*DM, h, SQ, DM, 2048);
    }

    ln_k<<<SQ,128>>>(h, lnfg, lnfb, n);
    gemm_tc<1><<<dim3(16,16,1),256>>>(n,DM,0, Wi,1024,0, fi,1024,0, bi, nullptr, SQ, 1024, DM);
    gemm_tc<0><<<dim3(7,16,1),256>>>(fi,1024,0, Wf,390,0, out,390,0, bf, nullptr, SQ, 390, 1024);
}

// round 8
// speedup vs baseline: 2.0911x; 1.1744x over previous
#include <cuda_runtime.h>
#include <math.h>
#include <stdint.h>

// Problem constants
#define SQ    1024      // sequence length
#define DM    512       // model dim
#define NH    8         // heads
#define HDIM  64        // head dim
#define NLAY  4         // layers
#define QK_SCALE 0.125f // 1/sqrt(64)

// ---------------------------------------------------------------------------
// Scratch (no allocations allowed -> __device__ globals)
// ---------------------------------------------------------------------------
__device__ float g_h [SQ*DM];
__device__ float g_n [SQ*DM];
__device__ float g_q [SQ*DM];
__device__ float g_k [SQ*DM];
__device__ float g_v [SQ*DM];
__device__ float g_ao[SQ*DM];
__device__ float g_f1[SQ*2048];
__device__ float g_fi[SQ*1024];
__device__ float g_sc[(size_t)NH*SQ*SQ];   // 32 MB attention scores

__device__ __forceinline__ float gelu_f(float x){
    return 0.5f*x*(1.f + erff(x*0.7071067811865476f));
}

__device__ __forceinline__ uint32_t f2tf(float x){
    uint32_t u; asm("cvt.rna.tf32.f32 %0, %1;" : "=r"(u) : "f"(x)); return u;
}

__device__ __forceinline__ void mma_tf32(float c[4],
    uint32_t a0, uint32_t a1, uint32_t a2, uint32_t a3,
    uint32_t b0, uint32_t b1)
{
    asm volatile(
        "mma.sync.aligned.m16n8k8.row.col.f32.tf32.tf32.f32 "
        "{%0,%1,%2,%3}, {%4,%5,%6,%7}, {%8,%9}, {%0,%1,%2,%3};"
        : "+f"(c[0]), "+f"(c[1]), "+f"(c[2]), "+f"(c[3])
        : "r"(a0), "r"(a1), "r"(a2), "r"(a3), "r"(b0), "r"(b1));
}

__device__ __forceinline__ void cp16(uint32_t smem_dst, const void* gsrc){
    asm volatile("cp.async.cg.shared.global [%0], [%1], 16;\n"
                 :: "r"(smem_dst), "l"(gsrc));
}
// predicate-off: size 0 AND clamped (valid) source address -> never OOB
__device__ __forceinline__ void cp4z(uint32_t smem_dst, const void* gsrc, bool pred){
    int sz = pred ? 4 : 0;
    asm volatile("cp.async.ca.shared.global [%0], [%1], 4, %2;\n"
                 :: "r"(smem_dst), "l"(gsrc), "r"(sz));
}
__device__ __forceinline__ void cp_commit(){
    asm volatile("cp.async.commit_group;\n" ::: "memory");
}

// ---------------------------------------------------------------------------
// 3xTF32 tensor-core GEMM core with cp.async 4-stage smem pipeline.
// smem holds raw fp32 tiles; hi/lo tf32 split happens in registers at consume.
// Block tile 64x64, BK=16, 256 threads = 8 warps (4x2), warp tile 16x32.
// EPI: 0 = bias, 1 = bias+gelu, 2 = bias+residual-add
// ---------------------------------------------------------------------------
template<int EPI>
__device__ __forceinline__ void gemm_core(
    const float* __restrict__ A, int lda,
    const float* __restrict__ B, int ldb,
    float* __restrict__ C, int ldc,
    const float* __restrict__ bias,
    const float* __restrict__ res,
    int M, int N, int K, int row0, int col0)
{
    constexpr int ST = 4;
    __shared__ float As[ST][64*20];   // [m][k] stride 20
    __shared__ float Bs[ST][16*72];   // [k][n] stride 72

    const int tid  = threadIdx.x;
    const int lane = tid & 31;
    const int w    = tid >> 5;
    const int wm   = w & 3;
    const int wn   = w >> 2;
    const int g    = lane >> 2;
    const int t    = lane & 3;

    float acc[4][4] = {};

    // A loader: one 16B chunk per thread (64 rows x 4 quads along K)
    const int ar  = tid >> 2;
    const int ac4 = (tid & 3) * 4;
    const float* Aptr = A + (long)(row0+ar)*lda + ac4;

    // B loader (vector path): 16 rows x 16 quads along N
    const int br  = tid >> 4;
    const int bc4 = (tid & 15) * 4;
    const bool vecB = ((ldb & 3) == 0) && (col0 + 64 <= N);
    const float* Bv = B + (long)br*ldb + col0 + bc4;
    // scalar path mapping (4 elems/thread)
    int sr[4], scc[4]; bool sp[4];
    if (!vecB){
        #pragma unroll
        for (int j = 0; j < 4; j++){
            int idx = tid + j*256;
            sr[j] = idx >> 6; scc[j] = idx & 63;
            sp[j] = (col0 + scc[j]) < N;
        }
    }

    const int ntiles = K >> 4;

    auto issue = [&](int k0, int s){
        uint32_t ad = (uint32_t)__cvta_generic_to_shared(&As[s][ar*20 + ac4]);
        cp16(ad, Aptr + k0);
        if (vecB){
            uint32_t bd = (uint32_t)__cvta_generic_to_shared(&Bs[s][br*72 + bc4]);
            cp16(bd, Bv + (long)k0*ldb);
        } else {
            #pragma unroll
            for (int j = 0; j < 4; j++){
                uint32_t bd = (uint32_t)__cvta_generic_to_shared(&Bs[s][sr[j]*72 + scc[j]]);
                // clamp source address to B when predicate off (no OOB address)
                const float* src = sp[j] ? (B + (long)(k0+sr[j])*ldb + col0 + scc[j]) : B;
                cp4z(bd, src, sp[j]);
            }
        }
        cp_commit();
    };

    // prologue: issue first ST-1 tiles
    issue(0, 0); issue(16, 1); issue(32, 2);

    const int mA0 = (wm*16 + g)*20;
    const int mA1 = (wm*16 + g + 8)*20;

    for (int kt = 0; kt < ntiles; kt++){
        int rem = ntiles - kt - 1;
        if (rem >= 2)      asm volatile("cp.async.wait_group 2;\n" ::: "memory");
        else if (rem == 1) asm volatile("cp.async.wait_group 1;\n" ::: "memory");
        else               asm volatile("cp.async.wait_group 0;\n" ::: "memory");
        __syncthreads();

        int nx = kt + ST - 1;
        if (nx < ntiles) issue(nx*16, nx & (ST-1));

        const float* Asl = As[kt & (ST-1)];
        const float* Bsl = Bs[kt & (ST-1)];

        #pragma unroll
        for (int ks = 0; ks < 16; ks += 8){
            float a0 = Asl[mA0 + ks + t    ];
            float a1 = Asl[mA1 + ks + t    ];
            float a2 = Asl[mA0 + ks + t + 4];
            float a3 = Asl[mA1 + ks + t + 4];
            uint32_t ah0 = f2tf(a0), ah1 = f2tf(a1), ah2 = f2tf(a2), ah3 = f2tf(a3);
            uint32_t al0 = f2tf(a0 - __uint_as_float(ah0));
            uint32_t al1 = f2tf(a1 - __uint_as_float(ah1));
            uint32_t al2 = f2tf(a2 - __uint_as_float(ah2));
            uint32_t al3 = f2tf(a3 - __uint_as_float(ah3));
            #pragma unroll
            for (int nt = 0; nt < 4; nt++){
                int bn = wn*32 + nt*8 + g;
                float b0 = Bsl[(ks + t    )*72 + bn];
                float b1 = Bsl[(ks + t + 4)*72 + bn];
                uint32_t bh0 = f2tf(b0), bh1 = f2tf(b1);
                uint32_t bl0 = f2tf(b0 - __uint_as_float(bh0));
                uint32_t bl1 = f2tf(b1 - __uint_as_float(bh1));
                mma_tf32(acc[nt], ah0, ah1, ah2, ah3, bh0, bh1);
                mma_tf32(acc[nt], ah0, ah1, ah2, ah3, bl0, bl1);
                mma_tf32(acc[nt], al0, al1, al2, al3, bh0, bh1);
            }
        }
    }

    // epilogue: c0:(g,2t) c1:(g,2t+1) c2:(g+8,2t) c3:(g+8,2t+1)
    const int r0 = row0 + wm*16 + g;
    const int r1 = r0 + 8;
    #pragma unroll
    for (int nt = 0; nt < 4; nt++){
        int col = col0 + wn*32 + nt*8 + 2*t;
        #pragma unroll
        for (int j = 0; j < 2; j++){
            int c = col + j;
            if (c < N){
                float v0 = acc[nt][j];
                float v1 = acc[nt][2+j];
                if (bias){ float bb = bias[c]; v0 += bb; v1 += bb; }
                if (EPI == 1){ v0 = gelu_f(v0); v1 = gelu_f(v1); }
                if (EPI == 2){
                    v0 += res[(long)r0*ldc + c];
                    v1 += res[(long)r1*ldc + c];
                }
                C[(long)r0*ldc + c] = v0;
                C[(long)r1*ldc + c] = v1;
            }
        }
    }
}

template<int EPI>
__global__ __launch_bounds__(256) void gemm_tc(
    const float* __restrict__ A, int lda, long sA,
    const float* __restrict__ B, int ldb, long sB,
    float* __restrict__ C, int ldc, long sC,
    const float* __restrict__ bias,
    const float* __restrict__ res,
    int M, int N, int K)
{
    const int z = blockIdx.z;
    gemm_core<EPI>(A + (long)z*sA, lda, B + (long)z*sB, ldb, C + (long)z*sC, ldc,
                   bias, (EPI==2) ? (res + (long)z*sC) : res,
                   M, N, K, blockIdx.y*64, blockIdx.x*64);
}

// Fused QKV: z picks (W, b, out); grid (8,16,3) = 384 blocks
__global__ __launch_bounds__(256) void gemm_qkv(
    const float* __restrict__ n,
    const float* __restrict__ Wq, const float* __restrict__ Wk, const float* __restrict__ Wv,
    const float* __restrict__ bq, const float* __restrict__ bk, const float* __restrict__ bv,
    float* __restrict__ q, float* __restrict__ k, float* __restrict__ v)
{
    const int z = blockIdx.z;
    const float* B    = (z==0) ? Wq : (z==1) ? Wk : Wv;
    const float* bias = (z==0) ? bq : (z==1) ? bk : bv;
    float*       C    = (z==0) ? q  : (z==1) ? k  : v;
    gemm_core<0>(n, DM, B, DM, C, DM, bias, nullptr,
                 SQ, DM, DM, blockIdx.y*64, blockIdx.x*64);
}

// ---------------------------------------------------------------------------
// LayerNorm over D=512. One block (128 threads, 1 float4 each) per row.
// ---------------------------------------------------------------------------
__global__ __launch_bounds__(128) void ln_k(
    const float* __restrict__ x, const float* __restrict__ g,
    const float* __restrict__ b, float* __restrict__ y)
{
    const int row = blockIdx.x, tid = threadIdx.x;
    float4 v = reinterpret_cast<const float4*>(x + (long)row*DM)[tid];
    float s  = v.x+v.y+v.z+v.w;
    float s2 = v.x*v.x+v.y*v.y+v.z*v.z+v.w*v.w;
    #pragma unroll
    for (int o = 16; o; o >>= 1){
        s  += __shfl_xor_sync(0xffffffffu, s,  o);
        s2 += __shfl_xor_sync(0xffffffffu, s2, o);
    }
    __shared__ float sh[8];
    if ((tid & 31) == 0){ sh[tid>>5] = s; sh[4 + (tid>>5)] = s2; }
    __syncthreads();
    s  = sh[0]+sh[1]+sh[2]+sh[3];
    s2 = sh[4]+sh[5]+sh[6]+sh[7];
    const float m = s * (1.f/DM);
    const float rstd = rsqrtf(s2*(1.f/DM) - m*m + 1e-5f);
    float4 gg = reinterpret_cast<const float4*>(g)[tid];
    float4 bb = reinterpret_cast<const float4*>(b)[tid];
    float4 o;
    o.x = (v.x-m)*rstd*gg.x + bb.x;
    o.y = (v.y-m)*rstd*gg.y + bb.y;
    o.z = (v.z-m)*rstd*gg.z + bb.z;
    o.w = (v.w-m)*rstd*gg.w + bb.w;
    reinterpret_cast<float4*>(y + (long)row*DM)[tid] = o;
}

// ---------------------------------------------------------------------------
// Fused attention scores: sc[h][s][t] = q_h[s].(scale*k_h[t]) + q_h[s].Er[s-t+1023]
// 64x64 tile, 4x4 microtile, d-major transposed smem -> 4x LDS.128 per d.
// Dynamic smem: qsT[64][68] + ksT[64][68] + esT[64][132] = 68608 B.
// ---------------------------------------------------------------------------
#define SCORES_SMEM ((64*68*2 + 64*132)*4)

__global__ __launch_bounds__(256) void scores_k(
    const float* __restrict__ q, const float* __restrict__ k,
    const float* __restrict__ Erl, float* __restrict__ sc)
{
    extern __shared__ float sm[];
    float* qsT = sm;               // [64][68] : qsT[d][s]
    float* ksT = sm + 64*68;       // [64][68] : ksT[d][t], pre-scaled
    float* esT = sm + 2*64*68;     // [64][132]: esT[d][r], r in 0..126

    const int h  = blockIdx.z;
    const int s0 = blockIdx.y*64, t0 = blockIdx.x*64;
    const int tid = threadIdx.x;

    #pragma unroll
    for (int i = 0; i < 16; i++){
        int idx = tid + i*256;           // 0..4095
        int r = idx >> 6, d = idx & 63;
        qsT[d*68 + r] = q[(long)(s0+r)*DM + h*HDIM + d];
        ksT[d*68 + r] = QK_SCALE * k[(long)(t0+r)*DM + h*HDIM + d];
    }
    // Er rows needed: rbase + 0..126, rbase = (s0-t0) + 1023 - 63
    const int rbase = s0 - t0 + 960;
    #pragma unroll
    for (int i = 0; i < 32; i++){
        int idx = tid + i*256;
        if (idx < 127*64){
            int r = idx >> 6, d = idx & 63;
            esT[d*132 + r] = Erl[(long)(rbase+r)*HDIM + d];
        }
    }
    __syncthreads();

    const int tx = tid & 15, ty = tid >> 4;
    const int s_ = ty*4, t_ = tx*4;
    const int rb0 = s_ - t_ + 60;        // multiple of 4, in [0,120]

    float acc[4][4] = {};
    #pragma unroll 4
    for (int d = 0; d < 64; d++){
        float4 qv = *(const float4*)&qsT[d*68 + s_];
        float4 kv = *(const float4*)&ksT[d*68 + t_];
        float4 e0 = *(const float4*)&esT[d*132 + rb0];
        float4 e1 = *(const float4*)&esT[d*132 + rb0 + 4];
        float qq[4] = {qv.x,qv.y,qv.z,qv.w};
        float kk[4] = {kv.x,kv.y,kv.z,kv.w};
        float ee[8] = {e0.x,e0.y,e0.z,e0.w,e1.x,e1.y,e1.z,e1.w};
        #pragma unroll
        for (int i = 0; i < 4; i++)
            #pragma unroll
            for (int j = 0; j < 4; j++)
                acc[i][j] = fmaf(qq[i], kk[j] + ee[i-j+3], acc[i][j]);
    }

    float* out = sc + (long)h*SQ*SQ;
    #pragma unroll
    for (int i = 0; i < 4; i++){
        float4 o = make_float4(acc[i][0], acc[i][1], acc[i][2], acc[i][3]);
        *(float4*)&out[(long)(s0+s_+i)*SQ + (t0+t_)] = o;
    }
}

// ---------------------------------------------------------------------------
// Row softmax over 1024 cols. One block (256 threads, 1 float4 each) per row.
// ---------------------------------------------------------------------------
__global__ __launch_bounds__(256) void softmax_k(float* __restrict__ sc)
{
    const long row = blockIdx.x;
    float4* p = reinterpret_cast<float4*>(sc + row*(long)SQ);
    const int tid = threadIdx.x;
    float4 v = p[tid];
    float mx = fmaxf(fmaxf(v.x,v.y), fmaxf(v.z,v.w));
    #pragma unroll
    for (int o = 16; o; o >>= 1) mx = fmaxf(mx, __shfl_xor_sync(0xffffffffu, mx, o));
    __shared__ float sh[8];
    if ((tid & 31) == 0) sh[tid>>5] = mx;
    __syncthreads();
    mx = fmaxf(fmaxf(fmaxf(sh[0],sh[1]), fmaxf(sh[2],sh[3])),
               fmaxf(fmaxf(sh[4],sh[5]), fmaxf(sh[6],sh[7])));
    __syncthreads();
    v.x = expf(v.x - mx); v.y = expf(v.y - mx);
    v.z = expf(v.z - mx); v.w = expf(v.w - mx);
    float s = v.x+v.y+v.z+v.w;
    #pragma unroll
    for (int o = 16; o; o >>= 1) s += __shfl_xor_sync(0xffffffffu, s, o);
    if ((tid & 31) == 0) sh[tid>>5] = s;
    __syncthreads();
    s = sh[0]+sh[1]+sh[2]+sh[3]+sh[4]+sh[5]+sh[6]+sh[7];
    const float inv = 1.f/s;
    v.x *= inv; v.y *= inv; v.z *= inv; v.w *= inv;
    p[tid] = v;
}

// ---------------------------------------------------------------------------
// Host orchestration
// ---------------------------------------------------------------------------
extern "C" void kernel_launch(void* const* d_in, const int* in_sizes, int n_in,
                              void* d_out, int out_size)
{
    const float* x     = (const float*)d_in[0];
    const float* emb_W = (const float*)d_in[1];
    const float* emb_b = (const float*)d_in[2];
    const float* Wq    = (const float*)d_in[3];
    const float* bq    = (const float*)d_in[4];
    const float* Wk    = (const float*)d_in[5];
    const float* bk    = (const float*)d_in[6];
    const float* Wv    = (const float*)d_in[7];
    const float* bv    = (const float*)d_in[8];
    const float* Wo    = (const float*)d_in[9];
    const float* bo    = (const float*)d_in[10];
    const float* Er    = (const float*)d_in[11];
    const float* ln1g  = (const float*)d_in[12];
    const float* ln1b  = (const float*)d_in[13];
    const float* W1    = (const float*)d_in[14];
    const float* b1    = (const float*)d_in[15];
    const float* W2    = (const float*)d_in[16];
    const float* b2    = (const float*)d_in[17];
    const float* ln2g  = (const float*)d_in[18];
    const float* ln2b  = (const float*)d_in[19];
    const float* lnfg  = (const float*)d_in[20];
    const float* lnfb  = (const float*)d_in[21];
    const float* Wi    = (const float*)d_in[22];
    const float* bi    = (const float*)d_in[23];
    const float* Wf    = (const float*)d_in[24];
    const float* bf    = (const float*)d_in[25];
    float* out = (float*)d_out;

    float *h, *n, *q, *k, *v, *ao, *f1, *fi, *sc;
    cudaGetSymbolAddress((void**)&h,  g_h);
    cudaGetSymbolAddress((void**)&n,  g_n);
    cudaGetSymbolAddress((void**)&q,  g_q);
    cudaGetSymbolAddress((void**)&k,  g_k);
    cudaGetSymbolAddress((void**)&v,  g_v);
    cudaGetSymbolAddress((void**)&ao, g_ao);
    cudaGetSymbolAddress((void**)&f1, g_f1);
    cudaGetSymbolAddress((void**)&fi, g_fi);
    cudaGetSymbolAddress((void**)&sc, g_sc);

    cudaFuncSetAttribute(scores_k, cudaFuncAttributeMaxDynamicSharedMemorySize, SCORES_SMEM);

    // embed: h = x @ emb_W + emb_b
    gemm_tc<0><<<dim3(8,16,1), 256>>>(x,128,0, emb_W,512,0, h,512,0,
                                      emb_b, nullptr, SQ, DM, 128);

    for (int l = 0; l < NLAY; l++) {
        const float* Wq_l = Wq + (long)l*DM*DM;
        const float* Wk_l = Wk + (long)l*DM*DM;
        const float* Wv_l = Wv + (long)l*DM*DM;
        const float* Wo_l = Wo + (long)l*DM*DM;
        const float* Er_l = Er + (long)l*2047*HDIM;
        const float* W1_l = W1 + (long)l*DM*2048;
        const float* W2_l = W2 + (long)l*2048*DM;

        ln_k<<<SQ,128>>>(h, ln1g + l*DM, ln1b + l*DM, n);

        // fused q,k,v projection
        gemm_qkv<<<dim3(8,16,3),256>>>(n, Wq_l, Wk_l, Wv_l,
                                       bq + l*DM, bk + l*DM, bv + l*DM, q, k, v);

        scores_k<<<dim3(16,16,NH),256,SCORES_SMEM>>>(q, k, Er_l, sc);
        softmax_k<<<NH*SQ,256>>>(sc);

        // ao = attn @ v (per head)
        gemm_tc<0><<<dim3(1,16,NH),256>>>(sc,SQ,(long)SQ*SQ, v,DM,HDIM, ao,DM,HDIM,
                                          nullptr, nullptr, SQ, HDIM, SQ);

        // h = h + ao @ Wo + bo
        gemm_tc<2><<<dim3(8,16,1),256>>>(ao,DM,0, Wo_l,DM,0, h,DM,0, bo + l*DM, h, SQ, DM, DM);

        ln_k<<<SQ,128>>>(h, ln2g + l*DM, ln2b + l*DM, n);

        // f1 = gelu(n @ W1 + b1)
        gemm_tc<1><<<dim3(32,16,1),256>>>(n,DM,0, W1_l,2048,0, f1,2048,0, b1 + l*2048, nullptr, SQ, 2048, DM);

        // h = h + f1 @ W2 + b2
        gemm_tc<2><<<dim3(8,16,1),256>>>(f1,2048,0, W2_l,DM,0, h,DM,0, b2 + l*DM, h, SQ, DM, 2048);
    }

    ln_k<<<SQ,128>>>(h, lnfg, lnfb, n);
    gemm_tc<1><<<dim3(16,16,1),256>>>(n,DM,0, Wi,1024,0, fi,1024,0, bi, nullptr, SQ, 1024, DM);
    gemm_tc<0><<<dim3(7,16,1),256>>>(fi,1024,0, Wf,390,0, out,390,0, bf, nullptr, SQ, 390, 1024);
}

// round 9
// speedup vs baseline: 2.1635x; 1.0346x over previous
#include <cuda_runtime.h>
#include <math.h>
#include <stdint.h>

// Problem constants
#define SQ    1024      // sequence length
#define DM    512       // model dim
#define NH    8         // heads
#define HDIM  64        // head dim
#define NLAY  4         // layers
#define QK_SCALE 0.125f // 1/sqrt(64)

// ---------------------------------------------------------------------------
// Scratch (no allocations allowed -> __device__ globals)
// ---------------------------------------------------------------------------
__device__ float g_h [SQ*DM];
__device__ float g_n [SQ*DM];
__device__ float g_q [SQ*DM];
__device__ float g_k [SQ*DM];
__device__ float g_v [SQ*DM];
__device__ float g_ao[SQ*DM];
__device__ float g_f1[SQ*2048];
__device__ float g_fi[SQ*1024];

__device__ __forceinline__ float gelu_f(float x){
    return 0.5f*x*(1.f + erff(x*0.7071067811865476f));
}

__device__ __forceinline__ uint32_t f2tf(float x){
    uint32_t u; asm("cvt.rna.tf32.f32 %0, %1;" : "=r"(u) : "f"(x)); return u;
}
__device__ __forceinline__ void split_tf(float x, uint32_t& hi, uint32_t& lo){
    hi = f2tf(x);
    lo = f2tf(x - __uint_as_float(hi));
}

__device__ __forceinline__ void mma_tf32(float c[4],
    uint32_t a0, uint32_t a1, uint32_t a2, uint32_t a3,
    uint32_t b0, uint32_t b1)
{
    asm volatile(
        "mma.sync.aligned.m16n8k8.row.col.f32.tf32.tf32.f32 "
        "{%0,%1,%2,%3}, {%4,%5,%6,%7}, {%8,%9}, {%0,%1,%2,%3};"
        : "+f"(c[0]), "+f"(c[1]), "+f"(c[2]), "+f"(c[3])
        : "r"(a0), "r"(a1), "r"(a2), "r"(a3), "r"(b0), "r"(b1));
}

__device__ __forceinline__ void cp16(uint32_t smem_dst, const void* gsrc){
    asm volatile("cp.async.cg.shared.global [%0], [%1], 16;\n"
                 :: "r"(smem_dst), "l"(gsrc));
}
// predicate-off: size 0 AND clamped (valid) source address -> never OOB
__device__ __forceinline__ void cp4z(uint32_t smem_dst, const void* gsrc, bool pred){
    int sz = pred ? 4 : 0;
    asm volatile("cp.async.ca.shared.global [%0], [%1], 4, %2;\n"
                 :: "r"(smem_dst), "l"(gsrc), "r"(sz));
}
__device__ __forceinline__ void cp_commit(){
    asm volatile("cp.async.commit_group;\n" ::: "memory");
}

// ---------------------------------------------------------------------------
// 3xTF32 tensor-core GEMM core with cp.async 4-stage smem pipeline (from R8).
// ---------------------------------------------------------------------------
template<int EPI>
__device__ __forceinline__ void gemm_core(
    const float* __restrict__ A, int lda,
    const float* __restrict__ B, int ldb,
    float* __restrict__ C, int ldc,
    const float* __restrict__ bias,
    const float* __restrict__ res,
    int M, int N, int K, int row0, int col0)
{
    constexpr int ST = 4;
    __shared__ float As[ST][64*20];   // [m][k] stride 20
    __shared__ float Bs[ST][16*72];   // [k][n] stride 72

    const int tid  = threadIdx.x;
    const int lane = tid & 31;
    const int w    = tid >> 5;
    const int wm   = w & 3;
    const int wn   = w >> 2;
    const int g    = lane >> 2;
    const int t    = lane & 3;

    float acc[4][4] = {};

    const int ar  = tid >> 2;
    const int ac4 = (tid & 3) * 4;
    const float* Aptr = A + (long)(row0+ar)*lda + ac4;

    const int br  = tid >> 4;
    const int bc4 = (tid & 15) * 4;
    const bool vecB = ((ldb & 3) == 0) && (col0 + 64 <= N);
    const float* Bv = B + (long)br*ldb + col0 + bc4;
    int sr[4], scc[4]; bool sp[4];
    if (!vecB){
        #pragma unroll
        for (int j = 0; j < 4; j++){
            int idx = tid + j*256;
            sr[j] = idx >> 6; scc[j] = idx & 63;
            sp[j] = (col0 + scc[j]) < N;
        }
    }

    const int ntiles = K >> 4;

    auto issue = [&](int k0, int s){
        uint32_t ad = (uint32_t)__cvta_generic_to_shared(&As[s][ar*20 + ac4]);
        cp16(ad, Aptr + k0);
        if (vecB){
            uint32_t bd = (uint32_t)__cvta_generic_to_shared(&Bs[s][br*72 + bc4]);
            cp16(bd, Bv + (long)k0*ldb);
        } else {
            #pragma unroll
            for (int j = 0; j < 4; j++){
                uint32_t bd = (uint32_t)__cvta_generic_to_shared(&Bs[s][sr[j]*72 + scc[j]]);
                const float* src = sp[j] ? (B + (long)(k0+sr[j])*ldb + col0 + scc[j]) : B;
                cp4z(bd, src, sp[j]);
            }
        }
        cp_commit();
    };

    issue(0, 0); issue(16, 1); issue(32, 2);

    const int mA0 = (wm*16 + g)*20;
    const int mA1 = (wm*16 + g + 8)*20;

    for (int kt = 0; kt < ntiles; kt++){
        int rem = ntiles - kt - 1;
        if (rem >= 2)      asm volatile("cp.async.wait_group 2;\n" ::: "memory");
        else if (rem == 1) asm volatile("cp.async.wait_group 1;\n" ::: "memory");
        else               asm volatile("cp.async.wait_group 0;\n" ::: "memory");
        __syncthreads();

        int nx = kt + ST - 1;
        if (nx < ntiles) issue(nx*16, nx & (ST-1));

        const float* Asl = As[kt & (ST-1)];
        const float* Bsl = Bs[kt & (ST-1)];

        #pragma unroll
        for (int ks = 0; ks < 16; ks += 8){
            float a0 = Asl[mA0 + ks + t    ];
            float a1 = Asl[mA1 + ks + t    ];
            float a2 = Asl[mA0 + ks + t + 4];
            float a3 = Asl[mA1 + ks + t + 4];
            uint32_t ah0,al0,ah1,al1,ah2,al2,ah3,al3;
            split_tf(a0,ah0,al0); split_tf(a1,ah1,al1);
            split_tf(a2,ah2,al2); split_tf(a3,ah3,al3);
            #pragma unroll
            for (int nt = 0; nt < 4; nt++){
                int bn = wn*32 + nt*8 + g;
                float b0 = Bsl[(ks + t    )*72 + bn];
                float b1 = Bsl[(ks + t + 4)*72 + bn];
                uint32_t bh0,bl0,bh1,bl1;
                split_tf(b0,bh0,bl0); split_tf(b1,bh1,bl1);
                mma_tf32(acc[nt], ah0, ah1, ah2, ah3, bh0, bh1);
                mma_tf32(acc[nt], ah0, ah1, ah2, ah3, bl0, bl1);
                mma_tf32(acc[nt], al0, al1, al2, al3, bh0, bh1);
            }
        }
    }

    const int r0 = row0 + wm*16 + g;
    const int r1 = r0 + 8;
    #pragma unroll
    for (int nt = 0; nt < 4; nt++){
        int col = col0 + wn*32 + nt*8 + 2*t;
        #pragma unroll
        for (int j = 0; j < 2; j++){
            int c = col + j;
            if (c < N){
                float v0 = acc[nt][j];
                float v1 = acc[nt][2+j];
                if (bias){ float bb = bias[c]; v0 += bb; v1 += bb; }
                if (EPI == 1){ v0 = gelu_f(v0); v1 = gelu_f(v1); }
                if (EPI == 2){
                    v0 += res[(long)r0*ldc + c];
                    v1 += res[(long)r1*ldc + c];
                }
                C[(long)r0*ldc + c] = v0;
                C[(long)r1*ldc + c] = v1;
            }
        }
    }
}

template<int EPI>
__global__ __launch_bounds__(256) void gemm_tc(
    const float* __restrict__ A, int lda, long sA,
    const float* __restrict__ B, int ldb, long sB,
    float* __restrict__ C, int ldc, long sC,
    const float* __restrict__ bias,
    const float* __restrict__ res,
    int M, int N, int K)
{
    const int z = blockIdx.z;
    gemm_core<EPI>(A + (long)z*sA, lda, B + (long)z*sB, ldb, C + (long)z*sC, ldc,
                   bias, (EPI==2) ? (res + (long)z*sC) : res,
                   M, N, K, blockIdx.y*64, blockIdx.x*64);
}

__global__ __launch_bounds__(256) void gemm_qkv(
    const float* __restrict__ n,
    const float* __restrict__ Wq, const float* __restrict__ Wk, const float* __restrict__ Wv,
    const float* __restrict__ bq, const float* __restrict__ bk, const float* __restrict__ bv,
    float* __restrict__ q, float* __restrict__ k, float* __restrict__ v)
{
    const int z = blockIdx.z;
    const float* B    = (z==0) ? Wq : (z==1) ? Wk : Wv;
    const float* bias = (z==0) ? bq : (z==1) ? bk : bv;
    float*       C    = (z==0) ? q  : (z==1) ? k  : v;
    gemm_core<0>(n, DM, B, DM, C, DM, bias, nullptr,
                 SQ, DM, DM, blockIdx.y*64, blockIdx.x*64);
}

// ---------------------------------------------------------------------------
// LayerNorm over D=512. One block (128 threads, 1 float4 each) per row.
// ---------------------------------------------------------------------------
__global__ __launch_bounds__(128) void ln_k(
    const float* __restrict__ x, const float* __restrict__ g,
    const float* __restrict__ b, float* __restrict__ y)
{
    const int row = blockIdx.x, tid = threadIdx.x;
    float4 v = reinterpret_cast<const float4*>(x + (long)row*DM)[tid];
    float s  = v.x+v.y+v.z+v.w;
    float s2 = v.x*v.x+v.y*v.y+v.z*v.z+v.w*v.w;
    #pragma unroll
    for (int o = 16; o; o >>= 1){
        s  += __shfl_xor_sync(0xffffffffu, s,  o);
        s2 += __shfl_xor_sync(0xffffffffu, s2, o);
    }
    __shared__ float sh[8];
    if ((tid & 31) == 0){ sh[tid>>5] = s; sh[4 + (tid>>5)] = s2; }
    __syncthreads();
    s  = sh[0]+sh[1]+sh[2]+sh[3];
    s2 = sh[4]+sh[5]+sh[6]+sh[7];
    const float m = s * (1.f/DM);
    const float rstd = rsqrtf(s2*(1.f/DM) - m*m + 1e-5f);
    float4 gg = reinterpret_cast<const float4*>(g)[tid];
    float4 bb = reinterpret_cast<const float4*>(b)[tid];
    float4 o;
    o.x = (v.x-m)*rstd*gg.x + bb.x;
    o.y = (v.y-m)*rstd*gg.y + bb.y;
    o.z = (v.z-m)*rstd*gg.z + bb.z;
    o.w = (v.w-m)*rstd*gg.w + bb.w;
    reinterpret_cast<float4*>(y + (long)row*DM)[tid] = o;
}

// ---------------------------------------------------------------------------
// Fused flash-style attention with relative position bias.
// One block per (64-query block, head). 256 threads = 8 warps (4m x 2n).
// Per 64-key tile:
//   S  = (Q K^T)*scale + gather(Q Er_band^T)   [3xTF32 mma]
//   online softmax (running max/sum, rescaled O)
//   O += P V                                   [3xTF32 mma]
// k/e/v tiles double-buffered via cp.async.
// ---------------------------------------------------------------------------
// smem float offsets
#define ATT_QS    0
#define ATT_KS    4352               // + 2*64*68
#define ATT_ES    (ATT_KS + 8704)    // + 2*128*68
#define ATT_VS    (ATT_ES + 17408)   // + 2*64*72
#define ATT_RS    (ATT_VS + 9216)    // + 64*132
#define ATT_PS    (ATT_RS + 8448)    // + 64*68
#define ATT_REDM  (ATT_PS + 4352)    // + 2*64
#define ATT_REDS  (ATT_REDM + 128)   // + 2*64
#define ATT_FLOATS (ATT_REDS + 128)
#define ATT_SMEM  (ATT_FLOATS*4)     // 210944 bytes

__global__ __launch_bounds__(256) void attn_k(
    const float* __restrict__ qg, const float* __restrict__ kg,
    const float* __restrict__ vg, const float* __restrict__ Erl,
    float* __restrict__ ao)
{
    extern __shared__ float sm[];
    float* qs   = sm + ATT_QS;     // [64][68]
    float* ksb  = sm + ATT_KS;     // [2][64][68]
    float* esb  = sm + ATT_ES;     // [2][128][68] (127 rows used)
    float* vsb  = sm + ATT_VS;     // [2][64][72]
    float* Rs   = sm + ATT_RS;     // [64][132]
    float* Ps   = sm + ATT_PS;     // [64][68]
    float* redm = sm + ATT_REDM;   // [2][64]
    float* reds = sm + ATT_REDS;   // [2][64]

    const int s0  = blockIdx.x * 64;
    const int h   = blockIdx.y;
    const int tid = threadIdx.x;
    const int lane = tid & 31, w = tid >> 5;
    const int wm = w & 3, wn = w >> 2;
    const int g = lane >> 2, t = lane & 3;

    // ---- load Q tile (once): rows s0..s0+63, dims h*64..h*64+63
    #pragma unroll
    for (int i = 0; i < 4; i++){
        int c = tid + i*256;                  // 0..1023
        int row = c >> 4, q4 = (c & 15) * 4;
        float4 v4 = *(const float4*)(qg + (long)(s0+row)*DM + h*HDIM + q4);
        qs[row*68 + q4 + 0] = v4.x; qs[row*68 + q4 + 1] = v4.y;
        qs[row*68 + q4 + 2] = v4.z; qs[row*68 + q4 + 3] = v4.w;
    }

    auto issue_tile = [&](int t0, int st){
        float* ksd = ksb + st*4352;
        float* esd = esb + st*8704;
        float* vsd = vsb + st*4608;
        const int rbase = s0 - t0 + 960;      // Er band start (0..1920)
        #pragma unroll
        for (int i = 0; i < 4; i++){
            int c = tid + i*256;
            int row = c >> 4, q4 = (c & 15) * 4;
            cp16((uint32_t)__cvta_generic_to_shared(&ksd[row*68 + q4]),
                 kg + (long)(t0+row)*DM + h*HDIM + q4);
            cp16((uint32_t)__cvta_generic_to_shared(&vsd[row*72 + q4]),
                 vg + (long)(t0+row)*DM + h*HDIM + q4);
        }
        #pragma unroll
        for (int i = 0; i < 8; i++){
            int c = tid + i*256;              // 0..2047; need 127*16=2032
            if (c < 2032){
                int row = c >> 4, q4 = (c & 15) * 4;
                cp16((uint32_t)__cvta_generic_to_shared(&esd[row*68 + q4]),
                     Erl + (long)(rbase+row)*HDIM + q4);
            }
        }
        cp_commit();
    };

    float O[4][4] = {};
    float m0 = -1e30f, m1 = -1e30f, l0 = 0.f, l1 = 0.f;
    const int r0 = wm*16 + g, r1 = r0 + 8;    // local query rows this thread owns

    issue_tile(0, 0);

    for (int it = 0; it < 16; it++){
        const int st = it & 1;
        asm volatile("cp.async.wait_group 0;\n" ::: "memory");
        __syncthreads();                                       // S1
        if (it < 15) issue_tile((it+1)*64, st ^ 1);

        const float* ksl = ksb + st*4352;
        const float* esl = esb + st*8704;
        const float* vsl = vsb + st*4608;

        // ---- QK + QE mma
        float accS[4][4] = {};
        float accR[2][4][4] = {};
        #pragma unroll
        for (int kk = 0; kk < 64; kk += 8){
            float a0 = qs[r0*68 + kk + t];
            float a1 = qs[r1*68 + kk + t];
            float a2 = qs[r0*68 + kk + t + 4];
            float a3 = qs[r1*68 + kk + t + 4];
            uint32_t ah0,al0,ah1,al1,ah2,al2,ah3,al3;
            split_tf(a0,ah0,al0); split_tf(a1,ah1,al1);
            split_tf(a2,ah2,al2); split_tf(a3,ah3,al3);
            #pragma unroll
            for (int nt = 0; nt < 4; nt++){
                int bn = wn*32 + nt*8 + g;
                float b0 = ksl[bn*68 + kk + t];
                float b1 = ksl[bn*68 + kk + t + 4];
                uint32_t bh0,bl0,bh1,bl1;
                split_tf(b0,bh0,bl0); split_tf(b1,bh1,bl1);
                mma_tf32(accS[nt], ah0,ah1,ah2,ah3, bh0,bh1);
                mma_tf32(accS[nt], ah0,ah1,ah2,ah3, bl0,bl1);
                mma_tf32(accS[nt], al0,al1,al2,al3, bh0,bh1);
            }
            #pragma unroll
            for (int nh = 0; nh < 2; nh++)
            #pragma unroll
            for (int nt = 0; nt < 4; nt++){
                int bn = nh*64 + wn*32 + nt*8 + g;
                float b0 = esl[bn*68 + kk + t];
                float b1 = esl[bn*68 + kk + t + 4];
                uint32_t bh0,bl0,bh1,bl1;
                split_tf(b0,bh0,bl0); split_tf(b1,bh1,bl1);
                mma_tf32(accR[nh][nt], ah0,ah1,ah2,ah3, bh0,bh1);
                mma_tf32(accR[nh][nt], ah0,ah1,ah2,ah3, bl0,bl1);
                mma_tf32(accR[nh][nt], al0,al1,al2,al3, bh0,bh1);
            }
        }

        // ---- store R (q . Er_band) to smem
        #pragma unroll
        for (int nh = 0; nh < 2; nh++)
        #pragma unroll
        for (int nt = 0; nt < 4; nt++){
            int u0 = nh*64 + wn*32 + nt*8 + 2*t;
            Rs[r0*132 + u0    ] = accR[nh][nt][0];
            Rs[r0*132 + u0 + 1] = accR[nh][nt][1];
            Rs[r1*132 + u0    ] = accR[nh][nt][2];
            Rs[r1*132 + u0 + 1] = accR[nh][nt][3];
        }
        __syncthreads();                                       // S2

        // ---- logits = scale*QK + gather(R); row max (partial)
        float tm0 = -1e30f, tm1 = -1e30f;
        #pragma unroll
        for (int nt = 0; nt < 4; nt++){
            #pragma unroll
            for (int j = 0; j < 2; j++){
                int tj = wn*32 + nt*8 + 2*t + j;
                float x0 = accS[nt][j]   * QK_SCALE + Rs[r0*132 + (r0 - tj + 63)];
                float x1 = accS[nt][2+j] * QK_SCALE + Rs[r1*132 + (r1 - tj + 63)];
                accS[nt][j]   = x0;
                accS[nt][2+j] = x1;
                tm0 = fmaxf(tm0, x0);
                tm1 = fmaxf(tm1, x1);
            }
        }
        tm0 = fmaxf(tm0, __shfl_xor_sync(0xffffffffu, tm0, 1));
        tm0 = fmaxf(tm0, __shfl_xor_sync(0xffffffffu, tm0, 2));
        tm1 = fmaxf(tm1, __shfl_xor_sync(0xffffffffu, tm1, 1));
        tm1 = fmaxf(tm1, __shfl_xor_sync(0xffffffffu, tm1, 2));
        if (t == 0){ redm[wn*64 + r0] = tm0; redm[wn*64 + r1] = tm1; }
        __syncthreads();                                       // S3

        float M0 = fmaxf(m0, fmaxf(redm[r0], redm[64 + r0]));
        float M1 = fmaxf(m1, fmaxf(redm[r1], redm[64 + r1]));

        // ---- exp, partial sums, write P
        float sum0 = 0.f, sum1 = 0.f;
        #pragma unroll
        for (int nt = 0; nt < 4; nt++){
            #pragma unroll
            for (int j = 0; j < 2; j++){
                int tj = wn*32 + nt*8 + 2*t + j;
                float p0 = expf(accS[nt][j]   - M0);
                float p1 = expf(accS[nt][2+j] - M1);
                sum0 += p0; sum1 += p1;
                Ps[r0*68 + tj] = p0;
                Ps[r1*68 + tj] = p1;
            }
        }
        sum0 += __shfl_xor_sync(0xffffffffu, sum0, 1);
        sum0 += __shfl_xor_sync(0xffffffffu, sum0, 2);
        sum1 += __shfl_xor_sync(0xffffffffu, sum1, 1);
        sum1 += __shfl_xor_sync(0xffffffffu, sum1, 2);
        if (t == 0){ reds[wn*64 + r0] = sum0; reds[wn*64 + r1] = sum1; }

        // ---- rescale O by exp(m_old - m_new)
        float f0 = expf(m0 - M0), f1 = expf(m1 - M1);
        #pragma unroll
        for (int nt = 0; nt < 4; nt++){
            O[nt][0] *= f0; O[nt][1] *= f0;
            O[nt][2] *= f1; O[nt][3] *= f1;
        }
        __syncthreads();                                       // S4

        l0 = l0*f0 + reds[r0] + reds[64 + r0];
        l1 = l1*f1 + reds[r1] + reds[64 + r1];
        m0 = M0; m1 = M1;

        // ---- O += P @ V
        #pragma unroll
        for (int kk = 0; kk < 64; kk += 8){
            float a0 = Ps[r0*68 + kk + t];
            float a1 = Ps[r1*68 + kk + t];
            float a2 = Ps[r0*68 + kk + t + 4];
            float a3 = Ps[r1*68 + kk + t + 4];
            uint32_t ah0,al0,ah1,al1,ah2,al2,ah3,al3;
            split_tf(a0,ah0,al0); split_tf(a1,ah1,al1);
            split_tf(a2,ah2,al2); split_tf(a3,ah3,al3);
            #pragma unroll
            for (int nt = 0; nt < 4; nt++){
                int bn = wn*32 + nt*8 + g;
                float b0 = vsl[(kk + t    )*72 + bn];
                float b1 = vsl[(kk + t + 4)*72 + bn];
                uint32_t bh0,bl0,bh1,bl1;
                split_tf(b0,bh0,bl0); split_tf(b1,bh1,bl1);
                mma_tf32(O[nt], ah0,ah1,ah2,ah3, bh0,bh1);
                mma_tf32(O[nt], ah0,ah1,ah2,ah3, bl0,bl1);
                mma_tf32(O[nt], al0,al1,al2,al3, bh0,bh1);
            }
        }
    }

    // ---- epilogue: O /= rowsum; write to ao[s][h*64+d]
    const float il0 = 1.f / l0, il1 = 1.f / l1;
    const int gr0 = s0 + r0, gr1 = s0 + r1;
    #pragma unroll
    for (int nt = 0; nt < 4; nt++){
        #pragma unroll
        for (int j = 0; j < 2; j++){
            int dc = h*HDIM + wn*32 + nt*8 + 2*t + j;
            ao[(long)gr0*DM + dc] = O[nt][j]   * il0;
            ao[(long)gr1*DM + dc] = O[nt][2+j] * il1;
        }
    }
}

// ---------------------------------------------------------------------------
// Host orchestration
// ---------------------------------------------------------------------------
extern "C" void kernel_launch(void* const* d_in, const int* in_sizes, int n_in,
                              void* d_out, int out_size)
{
    const float* x     = (const float*)d_in[0];
    const float* emb_W = (const float*)d_in[1];
    const float* emb_b = (const float*)d_in[2];
    const float* Wq    = (const float*)d_in[3];
    const float* bq    = (const float*)d_in[4];
    const float* Wk    = (const float*)d_in[5];
    const float* bk    = (const float*)d_in[6];
    const float* Wv    = (const float*)d_in[7];
    const float* bv    = (const float*)d_in[8];
    const float* Wo    = (const float*)d_in[9];
    const float* bo    = (const float*)d_in[10];
    const float* Er    = (const float*)d_in[11];
    const float* ln1g  = (const float*)d_in[12];
    const float* ln1b  = (const float*)d_in[13];
    const float* W1    = (const float*)d_in[14];
    const float* b1    = (const float*)d_in[15];
    const float* W2    = (const float*)d_in[16];
    const float* b2    = (const float*)d_in[17];
    const float* ln2g  = (const float*)d_in[18];
    const float* ln2b  = (const float*)d_in[19];
    const float* lnfg  = (const float*)d_in[20];
    const float* lnfb  = (const float*)d_in[21];
    const float* Wi    = (const float*)d_in[22];
    const float* bi    = (const float*)d_in[23];
    const float* Wf    = (const float*)d_in[24];
    const float* bf    = (const float*)d_in[25];
    float* out = (float*)d_out;

    float *h, *n, *q, *k, *v, *ao, *f1, *fi;
    cudaGetSymbolAddress((void**)&h,  g_h);
    cudaGetSymbolAddress((void**)&n,  g_n);
    cudaGetSymbolAddress((void**)&q,  g_q);
    cudaGetSymbolAddress((void**)&k,  g_k);
    cudaGetSymbolAddress((void**)&v,  g_v);
    cudaGetSymbolAddress((void**)&ao, g_ao);
    cudaGetSymbolAddress((void**)&f1, g_f1);
    cudaGetSymbolAddress((void**)&fi, g_fi);

    cudaFuncSetAttribute(attn_k, cudaFuncAttributeMaxDynamicSharedMemorySize, ATT_SMEM);

    // embed: h = x @ emb_W + emb_b
    gemm_tc<0><<<dim3(8,16,1), 256>>>(x,128,0, emb_W,512,0, h,512,0,
                                      emb_b, nullptr, SQ, DM, 128);

    for (int l = 0; l < NLAY; l++) {
        const float* Wq_l = Wq + (long)l*DM*DM;
        const float* Wk_l = Wk + (long)l*DM*DM;
        const float* Wv_l = Wv + (long)l*DM*DM;
        const float* Wo_l = Wo + (long)l*DM*DM;
        const float* Er_l = Er + (long)l*2047*HDIM;
        const float* W1_l = W1 + (long)l*DM*2048;
        const float* W2_l = W2 + (long)l*2048*DM;

        ln_k<<<SQ,128>>>(h, ln1g + l*DM, ln1b + l*DM, n);

        gemm_qkv<<<dim3(8,16,3),256>>>(n, Wq_l, Wk_l, Wv_l,
                                       bq + l*DM, bk + l*DM, bv + l*DM, q, k, v);

        // fused attention: scores + rel bias + softmax + @V
        attn_k<<<dim3(16,NH),256,ATT_SMEM>>>(q, k, v, Er_l, ao);

        // h = h + ao @ Wo + bo
        gemm_tc<2><<<dim3(8,16,1),256>>>(ao,DM,0, Wo_l,DM,0, h,DM,0, bo + l*DM, h, SQ, DM, DM);

        ln_k<<<SQ,128>>>(h, ln2g + l*DM, ln2b + l*DM, n);

        // f1 = gelu(n @ W1 + b1)
        gemm_tc<1><<<dim3(32,16,1),256>>>(n,DM,0, W1_l,2048,0, f1,2048,0, b1 + l*2048, nullptr, SQ, 2048, DM);

        // h = h + f1 @ W2 + b2
        gemm_tc<2><<<dim3(8,16,1),256>>>(f1,2048,0, W2_l,DM,0, h,DM,0, b2 + l*DM, h, SQ, DM, 2048);
    }

    ln_k<<<SQ,128>>>(h, lnfg, lnfb, n);
    gemm_tc<1><<<dim3(16,16,1),256>>>(n,DM,0, Wi,1024,0, fi,1024,0, bi, nullptr, SQ, 1024, DM);
    gemm_tc<0><<<dim3(7,16,1),256>>>(fi,1024,0, Wf,390,0, out,390,0, bf, nullptr, SQ, 390, 1024);
}

// round 10
// speedup vs baseline: 2.2190x; 1.0257x over previous
#include <cuda_runtime.h>
#include <math.h>
#include <stdint.h>

// Problem constants
#define SQ    1024      // sequence length
#define DM    512       // model dim
#define NH    8         // heads
#define HDIM  64        // head dim
#define NLAY  4         // layers
#define QK_SCALE 0.125f // 1/sqrt(64)

// ---------------------------------------------------------------------------
// Scratch (no allocations allowed -> __device__ globals)
// ---------------------------------------------------------------------------
__device__ float g_h [SQ*DM];
__device__ float g_n [SQ*DM];
__device__ float g_q [SQ*DM];
__device__ float g_k [SQ*DM];
__device__ float g_v [SQ*DM];
__device__ float g_ao[SQ*DM];
__device__ float g_f1[SQ*2048];
__device__ float g_fi[SQ*1024];
__device__ float g_erh[2047*HDIM];   // Er tf32-hi (per current layer)
__device__ float g_erl[2047*HDIM];   // Er tf32-lo

__device__ __forceinline__ float gelu_f(float x){
    return 0.5f*x*(1.f + erff(x*0.7071067811865476f));
}

__device__ __forceinline__ uint32_t f2tf(float x){
    uint32_t u; asm("cvt.rna.tf32.f32 %0, %1;" : "=r"(u) : "f"(x)); return u;
}
__device__ __forceinline__ void split_tf(float x, uint32_t& hi, uint32_t& lo){
    hi = f2tf(x);
    lo = f2tf(x - __uint_as_float(hi));
}

__device__ __forceinline__ void mma_tf32(float c[4],
    uint32_t a0, uint32_t a1, uint32_t a2, uint32_t a3,
    uint32_t b0, uint32_t b1)
{
    asm volatile(
        "mma.sync.aligned.m16n8k8.row.col.f32.tf32.tf32.f32 "
        "{%0,%1,%2,%3}, {%4,%5,%6,%7}, {%8,%9}, {%0,%1,%2,%3};"
        : "+f"(c[0]), "+f"(c[1]), "+f"(c[2]), "+f"(c[3])
        : "r"(a0), "r"(a1), "r"(a2), "r"(a3), "r"(b0), "r"(b1));
}

__device__ __forceinline__ void cp16(uint32_t smem_dst, const void* gsrc){
    asm volatile("cp.async.cg.shared.global [%0], [%1], 16;\n"
                 :: "r"(smem_dst), "l"(gsrc));
}
// predicate-off: size 0 AND clamped (valid) source address -> never OOB
__device__ __forceinline__ void cp4z(uint32_t smem_dst, const void* gsrc, bool pred){
    int sz = pred ? 4 : 0;
    asm volatile("cp.async.ca.shared.global [%0], [%1], 4, %2;\n"
                 :: "r"(smem_dst), "l"(gsrc), "r"(sz));
}
__device__ __forceinline__ void cp_commit(){
    asm volatile("cp.async.commit_group;\n" ::: "memory");
}

// ---------------------------------------------------------------------------
// 3xTF32 tensor-core GEMM core with cp.async 4-stage smem pipeline (from R8).
// ---------------------------------------------------------------------------
template<int EPI>
__device__ __forceinline__ void gemm_core(
    const float* __restrict__ A, int lda,
    const float* __restrict__ B, int ldb,
    float* __restrict__ C, int ldc,
    const float* __restrict__ bias,
    const float* __restrict__ res,
    int M, int N, int K, int row0, int col0)
{
    constexpr int ST = 4;
    __shared__ float As[ST][64*20];   // [m][k] stride 20
    __shared__ float Bs[ST][16*72];   // [k][n] stride 72

    const int tid  = threadIdx.x;
    const int lane = tid & 31;
    const int w    = tid >> 5;
    const int wm   = w & 3;
    const int wn   = w >> 2;
    const int g    = lane >> 2;
    const int t    = lane & 3;

    float acc[4][4] = {};

    const int ar  = tid >> 2;
    const int ac4 = (tid & 3) * 4;
    const float* Aptr = A + (long)(row0+ar)*lda + ac4;

    const int br  = tid >> 4;
    const int bc4 = (tid & 15) * 4;
    const bool vecB = ((ldb & 3) == 0) && (col0 + 64 <= N);
    const float* Bv = B + (long)br*ldb + col0 + bc4;
    int sr[4], scc[4]; bool sp[4];
    if (!vecB){
        #pragma unroll
        for (int j = 0; j < 4; j++){
            int idx = tid + j*256;
            sr[j] = idx >> 6; scc[j] = idx & 63;
            sp[j] = (col0 + scc[j]) < N;
        }
    }

    const int ntiles = K >> 4;

    auto issue = [&](int k0, int s){
        uint32_t ad = (uint32_t)__cvta_generic_to_shared(&As[s][ar*20 + ac4]);
        cp16(ad, Aptr + k0);
        if (vecB){
            uint32_t bd = (uint32_t)__cvta_generic_to_shared(&Bs[s][br*72 + bc4]);
            cp16(bd, Bv + (long)k0*ldb);
        } else {
            #pragma unroll
            for (int j = 0; j < 4; j++){
                uint32_t bd = (uint32_t)__cvta_generic_to_shared(&Bs[s][sr[j]*72 + scc[j]]);
                const float* src = sp[j] ? (B + (long)(k0+sr[j])*ldb + col0 + scc[j]) : B;
                cp4z(bd, src, sp[j]);
            }
        }
        cp_commit();
    };

    issue(0, 0); issue(16, 1); issue(32, 2);

    const int mA0 = (wm*16 + g)*20;
    const int mA1 = (wm*16 + g + 8)*20;

    for (int kt = 0; kt < ntiles; kt++){
        int rem = ntiles - kt - 1;
        if (rem >= 2)      asm volatile("cp.async.wait_group 2;\n" ::: "memory");
        else if (rem == 1) asm volatile("cp.async.wait_group 1;\n" ::: "memory");
        else               asm volatile("cp.async.wait_group 0;\n" ::: "memory");
        __syncthreads();

        int nx = kt + ST - 1;
        if (nx < ntiles) issue(nx*16, nx & (ST-1));

        const float* Asl = As[kt & (ST-1)];
        const float* Bsl = Bs[kt & (ST-1)];

        #pragma unroll
        for (int ks = 0; ks < 16; ks += 8){
            float a0 = Asl[mA0 + ks + t    ];
            float a1 = Asl[mA1 + ks + t    ];
            float a2 = Asl[mA0 + ks + t + 4];
            float a3 = Asl[mA1 + ks + t + 4];
            uint32_t ah0,al0,ah1,al1,ah2,al2,ah3,al3;
            split_tf(a0,ah0,al0); split_tf(a1,ah1,al1);
            split_tf(a2,ah2,al2); split_tf(a3,ah3,al3);
            #pragma unroll
            for (int nt = 0; nt < 4; nt++){
                int bn = wn*32 + nt*8 + g;
                float b0 = Bsl[(ks + t    )*72 + bn];
                float b1 = Bsl[(ks + t + 4)*72 + bn];
                uint32_t bh0,bl0,bh1,bl1;
                split_tf(b0,bh0,bl0); split_tf(b1,bh1,bl1);
                mma_tf32(acc[nt], ah0, ah1, ah2, ah3, bh0, bh1);
                mma_tf32(acc[nt], ah0, ah1, ah2, ah3, bl0, bl1);
                mma_tf32(acc[nt], al0, al1, al2, al3, bh0, bh1);
            }
        }
    }

    const int r0 = row0 + wm*16 + g;
    const int r1 = r0 + 8;
    #pragma unroll
    for (int nt = 0; nt < 4; nt++){
        int col = col0 + wn*32 + nt*8 + 2*t;
        #pragma unroll
        for (int j = 0; j < 2; j++){
            int c = col + j;
            if (c < N){
                float v0 = acc[nt][j];
                float v1 = acc[nt][2+j];
                if (bias){ float bb = bias[c]; v0 += bb; v1 += bb; }
                if (EPI == 1){ v0 = gelu_f(v0); v1 = gelu_f(v1); }
                if (EPI == 2){
                    v0 += res[(long)r0*ldc + c];
                    v1 += res[(long)r1*ldc + c];
                }
                C[(long)r0*ldc + c] = v0;
                C[(long)r1*ldc + c] = v1;
            }
        }
    }
}

template<int EPI>
__global__ __launch_bounds__(256) void gemm_tc(
    const float* __restrict__ A, int lda, long sA,
    const float* __restrict__ B, int ldb, long sB,
    float* __restrict__ C, int ldc, long sC,
    const float* __restrict__ bias,
    const float* __restrict__ res,
    int M, int N, int K)
{
    const int z = blockIdx.z;
    gemm_core<EPI>(A + (long)z*sA, lda, B + (long)z*sB, ldb, C + (long)z*sC, ldc,
                   bias, (EPI==2) ? (res + (long)z*sC) : res,
                   M, N, K, blockIdx.y*64, blockIdx.x*64);
}

__global__ __launch_bounds__(256) void gemm_qkv(
    const float* __restrict__ n,
    const float* __restrict__ Wq, const float* __restrict__ Wk, const float* __restrict__ Wv,
    const float* __restrict__ bq, const float* __restrict__ bk, const float* __restrict__ bv,
    float* __restrict__ q, float* __restrict__ k, float* __restrict__ v)
{
    const int z = blockIdx.z;
    const float* B    = (z==0) ? Wq : (z==1) ? Wk : Wv;
    const float* bias = (z==0) ? bq : (z==1) ? bk : bv;
    float*       C    = (z==0) ? q  : (z==1) ? k  : v;
    gemm_core<0>(n, DM, B, DM, C, DM, bias, nullptr,
                 SQ, DM, DM, blockIdx.y*64, blockIdx.x*64);
}

// ---------------------------------------------------------------------------
// Er tf32 hi/lo pre-split (once per layer): 2047*64 elements.
// ---------------------------------------------------------------------------
__global__ __launch_bounds__(256) void ersplit_k(
    const float* __restrict__ er, float* __restrict__ eh, float* __restrict__ el)
{
    int i = blockIdx.x*256 + threadIdx.x;
    if (i < 2047*HDIM){
        float x = er[i];
        uint32_t h, l; split_tf(x, h, l);
        eh[i] = __uint_as_float(h);
        el[i] = __uint_as_float(l);
    }
}

// ---------------------------------------------------------------------------
// LayerNorm over D=512. One block (128 threads, 1 float4 each) per row.
// ---------------------------------------------------------------------------
__global__ __launch_bounds__(128) void ln_k(
    const float* __restrict__ x, const float* __restrict__ g,
    const float* __restrict__ b, float* __restrict__ y)
{
    const int row = blockIdx.x, tid = threadIdx.x;
    float4 v = reinterpret_cast<const float4*>(x + (long)row*DM)[tid];
    float s  = v.x+v.y+v.z+v.w;
    float s2 = v.x*v.x+v.y*v.y+v.z*v.z+v.w*v.w;
    #pragma unroll
    for (int o = 16; o; o >>= 1){
        s  += __shfl_xor_sync(0xffffffffu, s,  o);
        s2 += __shfl_xor_sync(0xffffffffu, s2, o);
    }
    __shared__ float sh[8];
    if ((tid & 31) == 0){ sh[tid>>5] = s; sh[4 + (tid>>5)] = s2; }
    __syncthreads();
    s  = sh[0]+sh[1]+sh[2]+sh[3];
    s2 = sh[4]+sh[5]+sh[6]+sh[7];
    const float m = s * (1.f/DM);
    const float rstd = rsqrtf(s2*(1.f/DM) - m*m + 1e-5f);
    float4 gg = reinterpret_cast<const float4*>(g)[tid];
    float4 bb = reinterpret_cast<const float4*>(b)[tid];
    float4 o;
    o.x = (v.x-m)*rstd*gg.x + bb.x;
    o.y = (v.y-m)*rstd*gg.y + bb.y;
    o.z = (v.z-m)*rstd*gg.z + bb.z;
    o.w = (v.w-m)*rstd*gg.w + bb.w;
    reinterpret_cast<float4*>(y + (long)row*DM)[tid] = o;
}

// ---------------------------------------------------------------------------
// Fused flash-style attention with relative position bias (R10):
//  - Q pre-split to smem hi/lo once (loop-invariant)
//  - Er loaded as pre-split tf32 hi/lo from global (single-buffered; prefetch
//    issued after S2 so the load overlaps softmax + PV)
//  - P split at write; Ps aliases the dead R buffer (after S3)
//  - __expf softmax
// smem (floats): QH 4352 | QL 4352 | KS 2*4352 | EH 8704 | EL 8704 |
//                VS 2*4608 | RS 8704 (PsH/PsL alias) | redm 128 | reds 128
// ---------------------------------------------------------------------------
#define AQ_H   0
#define AQ_L   4352
#define AK     8704
#define AE_H   17408
#define AE_L   26112
#define AV     34816
#define AR     44032
#define AREDM  52736
#define AREDS  52864
#define ATT_FLOATS 52992
#define ATT_SMEM  (ATT_FLOATS*4)   // 211968 bytes

__global__ __launch_bounds__(256) void attn_k(
    const float* __restrict__ qg, const float* __restrict__ kg,
    const float* __restrict__ vg,
    const float* __restrict__ erh, const float* __restrict__ erl,
    float* __restrict__ ao)
{
    extern __shared__ float sm[];
    float* QH  = sm + AQ_H;      // [64][68] tf32-hi of Q
    float* QL  = sm + AQ_L;      // [64][68] tf32-lo of Q
    float* KS  = sm + AK;        // [2][64][68] raw fp32 K
    float* EH  = sm + AE_H;      // [128][68] tf32-hi Er band (127 rows used)
    float* EL  = sm + AE_L;      // [128][68] tf32-lo
    float* VS  = sm + AV;        // [2][64][72] raw fp32 V
    float* RS  = sm + AR;        // [64][136]; PsH/PsL alias after S3
    float* PH  = sm + AR;        // [64][68]
    float* PL  = sm + AR + 4352; // [64][68]
    float* redm = sm + AREDM;    // [2][64]
    float* reds = sm + AREDS;    // [2][64]

    const int s0  = blockIdx.x * 64;
    const int h   = blockIdx.y;
    const int tid = threadIdx.x;
    const int lane = tid & 31, w = tid >> 5;
    const int wm = w & 3, wn = w >> 2;
    const int g = lane >> 2, t = lane & 3;

    // ---- load + pre-split Q tile (once)
    #pragma unroll
    for (int i = 0; i < 4; i++){
        int c = tid + i*256;                  // 0..1023
        int row = c >> 4, q4 = (c & 15) * 4;
        float4 v4 = *(const float4*)(qg + (long)(s0+row)*DM + h*HDIM + q4);
        float xs[4] = {v4.x, v4.y, v4.z, v4.w};
        #pragma unroll
        for (int j = 0; j < 4; j++){
            uint32_t hh, ll; split_tf(xs[j], hh, ll);
            QH[row*68 + q4 + j] = __uint_as_float(hh);
            QL[row*68 + q4 + j] = __uint_as_float(ll);
        }
    }

    auto issue_kv = [&](int t0, int st){
        float* kd = KS + st*4352;
        float* vd = VS + st*4608;
        #pragma unroll
        for (int i = 0; i < 4; i++){
            int c = tid + i*256;
            int row = c >> 4, q4 = (c & 15) * 4;
            cp16((uint32_t)__cvta_generic_to_shared(&kd[row*68 + q4]),
                 kg + (long)(t0+row)*DM + h*HDIM + q4);
            cp16((uint32_t)__cvta_generic_to_shared(&vd[row*72 + q4]),
                 vg + (long)(t0+row)*DM + h*HDIM + q4);
        }
        cp_commit();
    };
    auto issue_e = [&](int t0){
        const int rbase = s0 - t0 + 960;      // Er band start (0..1920)
        #pragma unroll
        for (int i = 0; i < 8; i++){
            int c = tid + i*256;              // need 127*16 = 2032
            if (c < 2032){
                int row = c >> 4, q4 = (c & 15) * 4;
                cp16((uint32_t)__cvta_generic_to_shared(&EH[row*68 + q4]),
                     erh + (long)(rbase+row)*HDIM + q4);
                cp16((uint32_t)__cvta_generic_to_shared(&EL[row*68 + q4]),
                     erl + (long)(rbase+row)*HDIM + q4);
            }
        }
        cp_commit();
    };

    float O[4][4] = {};
    float m0 = -1e30f, m1 = -1e30f, l0 = 0.f, l1 = 0.f;
    const int r0 = wm*16 + g, r1 = r0 + 8;

    issue_kv(0, 0);
    issue_e(0);

    for (int it = 0; it < 16; it++){
        const int st = it & 1;
        asm volatile("cp.async.wait_group 0;\n" ::: "memory");
        __syncthreads();                                       // S1
        if (it < 15) issue_kv((it+1)*64, st ^ 1);

        const float* ksl = KS + st*4352;
        const float* vsl = VS + st*4608;

        // ---- QK + QE mma (Q from pre-split smem; Er from pre-split smem)
        float accS[4][4] = {};
        float accR[2][4][4] = {};
        #pragma unroll
        for (int kk = 0; kk < 64; kk += 8){
            uint32_t ah0 = __float_as_uint(QH[r0*68 + kk + t]);
            uint32_t ah1 = __float_as_uint(QH[r1*68 + kk + t]);
            uint32_t ah2 = __float_as_uint(QH[r0*68 + kk + t + 4]);
            uint32_t ah3 = __float_as_uint(QH[r1*68 + kk + t + 4]);
            uint32_t al0 = __float_as_uint(QL[r0*68 + kk + t]);
            uint32_t al1 = __float_as_uint(QL[r1*68 + kk + t]);
            uint32_t al2 = __float_as_uint(QL[r0*68 + kk + t + 4]);
            uint32_t al3 = __float_as_uint(QL[r1*68 + kk + t + 4]);
            #pragma unroll
            for (int nt = 0; nt < 4; nt++){
                int bn = wn*32 + nt*8 + g;
                float b0 = ksl[bn*68 + kk + t];
                float b1 = ksl[bn*68 + kk + t + 4];
                uint32_t bh0,bl0,bh1,bl1;
                split_tf(b0,bh0,bl0); split_tf(b1,bh1,bl1);
                mma_tf32(accS[nt], ah0,ah1,ah2,ah3, bh0,bh1);
                mma_tf32(accS[nt], ah0,ah1,ah2,ah3, bl0,bl1);
                mma_tf32(accS[nt], al0,al1,al2,al3, bh0,bh1);
            }
            #pragma unroll
            for (int nh = 0; nh < 2; nh++)
            #pragma unroll
            for (int nt = 0; nt < 4; nt++){
                int bn = nh*64 + wn*32 + nt*8 + g;
                uint32_t bh0 = __float_as_uint(EH[bn*68 + kk + t]);
                uint32_t bh1 = __float_as_uint(EH[bn*68 + kk + t + 4]);
                uint32_t bl0 = __float_as_uint(EL[bn*68 + kk + t]);
                uint32_t bl1 = __float_as_uint(EL[bn*68 + kk + t + 4]);
                mma_tf32(accR[nh][nt], ah0,ah1,ah2,ah3, bh0,bh1);
                mma_tf32(accR[nh][nt], ah0,ah1,ah2,ah3, bl0,bl1);
                mma_tf32(accR[nh][nt], al0,al1,al2,al3, bh0,bh1);
            }
        }

        // ---- store R (q . Er_band) to smem, stride 136
        #pragma unroll
        for (int nh = 0; nh < 2; nh++)
        #pragma unroll
        for (int nt = 0; nt < 4; nt++){
            int u0 = nh*64 + wn*32 + nt*8 + 2*t;
            RS[r0*136 + u0    ] = accR[nh][nt][0];
            RS[r0*136 + u0 + 1] = accR[nh][nt][1];
            RS[r1*136 + u0    ] = accR[nh][nt][2];
            RS[r1*136 + u0 + 1] = accR[nh][nt][3];
        }
        __syncthreads();                                       // S2
        // Er consumed; prefetch next band (overlaps softmax + PV)
        if (it < 15) issue_e((it+1)*64);

        // ---- logits = scale*QK + gather(R); row max (partial)
        float tm0 = -1e30f, tm1 = -1e30f;
        #pragma unroll
        for (int nt = 0; nt < 4; nt++){
            #pragma unroll
            for (int j = 0; j < 2; j++){
                int tj = wn*32 + nt*8 + 2*t + j;
                float x0 = accS[nt][j]   * QK_SCALE + RS[r0*136 + (r0 - tj + 63)];
                float x1 = accS[nt][2+j] * QK_SCALE + RS[r1*136 + (r1 - tj + 63)];
                accS[nt][j]   = x0;
                accS[nt][2+j] = x1;
                tm0 = fmaxf(tm0, x0);
                tm1 = fmaxf(tm1, x1);
            }
        }
        tm0 = fmaxf(tm0, __shfl_xor_sync(0xffffffffu, tm0, 1));
        tm0 = fmaxf(tm0, __shfl_xor_sync(0xffffffffu, tm0, 2));
        tm1 = fmaxf(tm1, __shfl_xor_sync(0xffffffffu, tm1, 1));
        tm1 = fmaxf(tm1, __shfl_xor_sync(0xffffffffu, tm1, 2));
        if (t == 0){ redm[wn*64 + r0] = tm0; redm[wn*64 + r1] = tm1; }
        __syncthreads();                                       // S3 (R dead after this)

        float M0 = fmaxf(m0, fmaxf(redm[r0], redm[64 + r0]));
        float M1 = fmaxf(m1, fmaxf(redm[r1], redm[64 + r1]));

        // ---- exp, partial sums; write P pre-split (aliases R region)
        float sum0 = 0.f, sum1 = 0.f;
        #pragma unroll
        for (int nt = 0; nt < 4; nt++){
            #pragma unroll
            for (int j = 0; j < 2; j++){
                int tj = wn*32 + nt*8 + 2*t + j;
                float p0 = __expf(accS[nt][j]   - M0);
                float p1 = __expf(accS[nt][2+j] - M1);
                sum0 += p0; sum1 += p1;
                uint32_t hh, ll;
                split_tf(p0, hh, ll);
                PH[r0*68 + tj] = __uint_as_float(hh);
                PL[r0*68 + tj] = __uint_as_float(ll);
                split_tf(p1, hh, ll);
                PH[r1*68 + tj] = __uint_as_float(hh);
                PL[r1*68 + tj] = __uint_as_float(ll);
            }
        }
        sum0 += __shfl_xor_sync(0xffffffffu, sum0, 1);
        sum0 += __shfl_xor_sync(0xffffffffu, sum0, 2);
        sum1 += __shfl_xor_sync(0xffffffffu, sum1, 1);
        sum1 += __shfl_xor_sync(0xffffffffu, sum1, 2);
        if (t == 0){ reds[wn*64 + r0] = sum0; reds[wn*64 + r1] = sum1; }

        // ---- rescale O by exp(m_old - m_new)
        float f0 = __expf(m0 - M0), f1 = __expf(m1 - M1);
        #pragma unroll
        for (int nt = 0; nt < 4; nt++){
            O[nt][0] *= f0; O[nt][1] *= f0;
            O[nt][2] *= f1; O[nt][3] *= f1;
        }
        __syncthreads();                                       // S4

        l0 = l0*f0 + reds[r0] + reds[64 + r0];
        l1 = l1*f1 + reds[r1] + reds[64 + r1];
        m0 = M0; m1 = M1;

        // ---- O += P @ V (P pre-split; V split at consume)
        #pragma unroll
        for (int kk = 0; kk < 64; kk += 8){
            uint32_t ah0 = __float_as_uint(PH[r0*68 + kk + t]);
            uint32_t ah1 = __float_as_uint(PH[r1*68 + kk + t]);
            uint32_t ah2 = __float_as_uint(PH[r0*68 + kk + t + 4]);
            uint32_t ah3 = __float_as_uint(PH[r1*68 + kk + t + 4]);
            uint32_t al0 = __float_as_uint(PL[r0*68 + kk + t]);
            uint32_t al1 = __float_as_uint(PL[r1*68 + kk + t]);
            uint32_t al2 = __float_as_uint(PL[r0*68 + kk + t + 4]);
            uint32_t al3 = __float_as_uint(PL[r1*68 + kk + t + 4]);
            #pragma unroll
            for (int nt = 0; nt < 4; nt++){
                int bn = wn*32 + nt*8 + g;
                float b0 = vsl[(kk + t    )*72 + bn];
                float b1 = vsl[(kk + t + 4)*72 + bn];
                uint32_t bh0,bl0,bh1,bl1;
                split_tf(b0,bh0,bl0); split_tf(b1,bh1,bl1);
                mma_tf32(O[nt], ah0,ah1,ah2,ah3, bh0,bh1);
                mma_tf32(O[nt], ah0,ah1,ah2,ah3, bl0,bl1);
                mma_tf32(O[nt], al0,al1,al2,al3, bh0,bh1);
            }
        }
    }

    // ---- epilogue: O /= rowsum; write to ao[s][h*64+d]
    const float il0 = 1.f / l0, il1 = 1.f / l1;
    const int gr0 = s0 + r0, gr1 = s0 + r1;
    #pragma unroll
    for (int nt = 0; nt < 4; nt++){
        #pragma unroll
        for (int j = 0; j < 2; j++){
            int dc = h*HDIM + wn*32 + nt*8 + 2*t + j;
            ao[(long)gr0*DM + dc] = O[nt][j]   * il0;
            ao[(long)gr1*DM + dc] = O[nt][2+j] * il1;
        }
    }
}

// ---------------------------------------------------------------------------
// Host orchestration
// ---------------------------------------------------------------------------
extern "C" void kernel_launch(void* const* d_in, const int* in_sizes, int n_in,
                              void* d_out, int out_size)
{
    const float* x     = (const float*)d_in[0];
    const float* emb_W = (const float*)d_in[1];
    const float* emb_b = (const float*)d_in[2];
    const float* Wq    = (const float*)d_in[3];
    const float* bq    = (const float*)d_in[4];
    const float* Wk    = (const float*)d_in[5];
    const float* bk    = (const float*)d_in[6];
    const float* Wv    = (const float*)d_in[7];
    const float* bv    = (const float*)d_in[8];
    const float* Wo    = (const float*)d_in[9];
    const float* bo    = (const float*)d_in[10];
    const float* Er    = (const float*)d_in[11];
    const float* ln1g  = (const float*)d_in[12];
    const float* ln1b  = (const float*)d_in[13];
    const float* W1    = (const float*)d_in[14];
    const float* b1    = (const float*)d_in[15];
    const float* W2    = (const float*)d_in[16];
    const float* b2    = (const float*)d_in[17];
    const float* ln2g  = (const float*)d_in[18];
    const float* ln2b  = (const float*)d_in[19];
    const float* lnfg  = (const float*)d_in[20];
    const float* lnfb  = (const float*)d_in[21];
    const float* Wi    = (const float*)d_in[22];
    const float* bi    = (const float*)d_in[23];
    const float* Wf    = (const float*)d_in[24];
    const float* bf    = (const float*)d_in[25];
    float* out = (float*)d_out;

    float *h, *n, *q, *k, *v, *ao, *f1, *fi, *erh, *erl;
    cudaGetSymbolAddress((void**)&h,  g_h);
    cudaGetSymbolAddress((void**)&n,  g_n);
    cudaGetSymbolAddress((void**)&q,  g_q);
    cudaGetSymbolAddress((void**)&k,  g_k);
    cudaGetSymbolAddress((void**)&v,  g_v);
    cudaGetSymbolAddress((void**)&ao, g_ao);
    cudaGetSymbolAddress((void**)&f1, g_f1);
    cudaGetSymbolAddress((void**)&fi, g_fi);
    cudaGetSymbolAddress((void**)&erh, g_erh);
    cudaGetSymbolAddress((void**)&erl, g_erl);

    cudaFuncSetAttribute(attn_k, cudaFuncAttributeMaxDynamicSharedMemorySize, ATT_SMEM);

    // embed: h = x @ emb_W + emb_b
    gemm_tc<0><<<dim3(8,16,1), 256>>>(x,128,0, emb_W,512,0, h,512,0,
                                      emb_b, nullptr, SQ, DM, 128);

    for (int l = 0; l < NLAY; l++) {
        const float* Wq_l = Wq + (long)l*DM*DM;
        const float* Wk_l = Wk + (long)l*DM*DM;
        const float* Wv_l = Wv + (long)l*DM*DM;
        const float* Wo_l = Wo + (long)l*DM*DM;
        const float* Er_l = Er + (long)l*2047*HDIM;
        const float* W1_l = W1 + (long)l*DM*2048;
        const float* W2_l = W2 + (long)l*2048*DM;

        ln_k<<<SQ,128>>>(h, ln1g + l*DM, ln1b + l*DM, n);

        gemm_qkv<<<dim3(8,16,3),256>>>(n, Wq_l, Wk_l, Wv_l,
                                       bq + l*DM, bk + l*DM, bv + l*DM, q, k, v);

        // pre-split Er for this layer, then fused attention
        ersplit_k<<<(2047*HDIM + 255)/256, 256>>>(Er_l, erh, erl);
        attn_k<<<dim3(16,NH),256,ATT_SMEM>>>(q, k, v, erh, erl, ao);

        // h = h + ao @ Wo + bo
        gemm_tc<2><<<dim3(8,16,1),256>>>(ao,DM,0, Wo_l,DM,0, h,DM,0, bo + l*DM, h, SQ, DM, DM);

        ln_k<<<SQ,128>>>(h, ln2g + l*DM, ln2b + l*DM, n);

        // f1 = gelu(n @ W1 + b1)
        gemm_tc<1><<<dim3(32,16,1),256>>>(n,DM,0, W1_l,2048,0, f1,2048,0, b1 + l*2048, nullptr, SQ, 2048, DM);

        // h = h + f1 @ W2 + b2
        gemm_tc<2><<<dim3(8,16,1),256>>>(f1,2048,0, W2_l,DM,0, h,DM,0, b2 + l*DM, h, SQ, DM, 2048);
    }

    ln_k<<<SQ,128>>>(h, lnfg, lnfb, n);
    gemm_tc<1><<<dim3(16,16,1),256>>>(n,DM,0, Wi,1024,0, fi,1024,0, bi, nullptr, SQ, 1024, DM);
    gemm_tc<0><<<dim3(7,16,1),256>>>(fi,1024,0, Wf,390,0, out,390,0, bf, nullptr, SQ, 390, 1024);
}

// round 11
// speedup vs baseline: 2.4524x; 1.1052x over previous
#include <cuda_runtime.h>
#include <math.h>
#include <stdint.h>

// Problem constants
#define SQ    1024      // sequence length
#define DM    512       // model dim
#define NH    8         // heads
#define HDIM  64        // head dim
#define NLAY  4         // layers
#define QK_SCALE 0.125f // 1/sqrt(64)

// ---------------------------------------------------------------------------
// Scratch (no allocations allowed -> __device__ globals)
// ---------------------------------------------------------------------------
__device__ float g_h [SQ*DM];
__device__ float g_n [SQ*DM];
__device__ float g_q [SQ*DM];
__device__ float g_k [SQ*DM];
__device__ float g_v [SQ*DM];
__device__ float g_ao[SQ*DM];
__device__ float g_f1[SQ*2048];
__device__ float g_fi[SQ*1024];

// pre-split weight store (tf32 hi/lo), all tensors concatenated (floats):
#define OFF_EMB 0
#define OFF_WQ  65536
#define OFF_WK  1114112
#define OFF_WV  2162688
#define OFF_WO  3211264
#define OFF_W1  4259840
#define OFF_W2  8454144
#define OFF_WI  12648448
#define OFF_WF  13172736
#define WTOT    13572096
__device__ float g_wh[WTOT];
__device__ float g_wl[WTOT];
__device__ float g_erh[NLAY*2047*HDIM];
__device__ float g_erl[NLAY*2047*HDIM];

__device__ __forceinline__ float gelu_f(float x){
    return 0.5f*x*(1.f + erff(x*0.7071067811865476f));
}

__device__ __forceinline__ uint32_t f2tf(float x){
    uint32_t u; asm("cvt.rna.tf32.f32 %0, %1;" : "=r"(u) : "f"(x)); return u;
}
__device__ __forceinline__ void split_tf(float x, uint32_t& hi, uint32_t& lo){
    hi = f2tf(x);
    lo = f2tf(x - __uint_as_float(hi));
}

__device__ __forceinline__ void mma_tf32(float c[4],
    uint32_t a0, uint32_t a1, uint32_t a2, uint32_t a3,
    uint32_t b0, uint32_t b1)
{
    asm volatile(
        "mma.sync.aligned.m16n8k8.row.col.f32.tf32.tf32.f32 "
        "{%0,%1,%2,%3}, {%4,%5,%6,%7}, {%8,%9}, {%0,%1,%2,%3};"
        : "+f"(c[0]), "+f"(c[1]), "+f"(c[2]), "+f"(c[3])
        : "r"(a0), "r"(a1), "r"(a2), "r"(a3), "r"(b0), "r"(b1));
}

__device__ __forceinline__ void cp16(uint32_t smem_dst, const void* gsrc){
    asm volatile("cp.async.cg.shared.global [%0], [%1], 16;\n"
                 :: "r"(smem_dst), "l"(gsrc));
}
// predicate-off: size 0 AND clamped (valid) source address -> never OOB
__device__ __forceinline__ void cp4z(uint32_t smem_dst, const void* gsrc, bool pred){
    int sz = pred ? 4 : 0;
    asm volatile("cp.async.ca.shared.global [%0], [%1], 4, %2;\n"
                 :: "r"(smem_dst), "l"(gsrc), "r"(sz));
}
__device__ __forceinline__ void cp_commit(){
    asm volatile("cp.async.commit_group;\n" ::: "memory");
}

// ---------------------------------------------------------------------------
// Weight tf32 hi/lo pre-split: float4 per thread.
// ---------------------------------------------------------------------------
__global__ __launch_bounds__(256) void wsplit_k(
    const float4* __restrict__ src, float4* __restrict__ dh,
    float4* __restrict__ dl, int n4)
{
    int i = blockIdx.x*256 + threadIdx.x;
    if (i < n4){
        float4 v = src[i];
        float xs[4] = {v.x, v.y, v.z, v.w};
        float hs[4], ls[4];
        #pragma unroll
        for (int j = 0; j < 4; j++){
            uint32_t h, l; split_tf(xs[j], h, l);
            hs[j] = __uint_as_float(h); ls[j] = __uint_as_float(l);
        }
        dh[i] = make_float4(hs[0],hs[1],hs[2],hs[3]);
        dl[i] = make_float4(ls[0],ls[1],ls[2],ls[3]);
    }
}

// ---------------------------------------------------------------------------
// 3xTF32 tensor-core GEMM, cp.async 3-stage pipeline, PRE-SPLIT B (weights).
// A raw fp32 (split at consume: cheap); B loaded as tf32 hi/lo directly.
// Block tile 64x64, BK=16, 256 threads = 8 warps (4x2), warp tile 16x32.
// EPI: 0 = bias, 1 = bias+gelu, 2 = bias+residual-add
// ---------------------------------------------------------------------------
template<int EPI>
__device__ __forceinline__ void gemm_core(
    const float* __restrict__ A, int lda,
    const float* __restrict__ Bh, const float* __restrict__ Bl, int ldb,
    float* __restrict__ C, int ldc,
    const float* __restrict__ bias,
    const float* __restrict__ res,
    int M, int N, int K, int row0, int col0)
{
    constexpr int ST = 3;
    __shared__ float As [ST][64*20];   // raw A,  [m][k] stride 20
    __shared__ float BhS[ST][16*72];   // tf32-hi B, [k][n] stride 72
    __shared__ float BlS[ST][16*72];   // tf32-lo B

    const int tid  = threadIdx.x;
    const int lane = tid & 31;
    const int w    = tid >> 5;
    const int wm   = w & 3;
    const int wn   = w >> 2;
    const int g    = lane >> 2;
    const int t    = lane & 3;

    float acc[4][4] = {};

    const int ar  = tid >> 2;
    const int ac4 = (tid & 3) * 4;
    const float* Aptr = A + (long)(row0+ar)*lda + ac4;

    const int br  = tid >> 4;
    const int bc4 = (tid & 15) * 4;
    const bool vecB = ((ldb & 3) == 0) && (col0 + 64 <= N);
    const float* Bvh = Bh + (long)br*ldb + col0 + bc4;
    const float* Bvl = Bl + (long)br*ldb + col0 + bc4;
    int sr[4], scc[4]; bool sp[4];
    if (!vecB){
        #pragma unroll
        for (int j = 0; j < 4; j++){
            int idx = tid + j*256;
            sr[j] = idx >> 6; scc[j] = idx & 63;
            sp[j] = (col0 + scc[j]) < N;
        }
    }

    const int ntiles = K >> 4;

    auto issue = [&](int k0, int s){
        cp16((uint32_t)__cvta_generic_to_shared(&As[s][ar*20 + ac4]), Aptr + k0);
        if (vecB){
            cp16((uint32_t)__cvta_generic_to_shared(&BhS[s][br*72 + bc4]),
                 Bvh + (long)k0*ldb);
            cp16((uint32_t)__cvta_generic_to_shared(&BlS[s][br*72 + bc4]),
                 Bvl + (long)k0*ldb);
        } else {
            #pragma unroll
            for (int j = 0; j < 4; j++){
                long go = (long)(k0+sr[j])*ldb + col0 + scc[j];
                cp4z((uint32_t)__cvta_generic_to_shared(&BhS[s][sr[j]*72 + scc[j]]),
                     sp[j] ? (Bh + go) : Bh, sp[j]);
                cp4z((uint32_t)__cvta_generic_to_shared(&BlS[s][sr[j]*72 + scc[j]]),
                     sp[j] ? (Bl + go) : Bl, sp[j]);
            }
        }
        cp_commit();
    };

    // prologue: 2 tiles in flight
    issue(0, 0); issue(16, 1);

    const int mA0 = (wm*16 + g)*20;
    const int mA1 = (wm*16 + g + 8)*20;

    int s = 0;                     // rotating stage index
    for (int kt = 0; kt < ntiles; kt++){
        if (kt + 1 < ntiles) asm volatile("cp.async.wait_group 1;\n" ::: "memory");
        else                 asm volatile("cp.async.wait_group 0;\n" ::: "memory");
        __syncthreads();

        int nx = kt + 2;
        if (nx < ntiles){
            int sn = s + 2; if (sn >= ST) sn -= ST;
            issue(nx*16, sn);
        }

        const float* Asl = As[s];
        const float* Bhl = BhS[s];
        const float* Bll = BlS[s];

        #pragma unroll
        for (int ks = 0; ks < 16; ks += 8){
            float a0 = Asl[mA0 + ks + t    ];
            float a1 = Asl[mA1 + ks + t    ];
            float a2 = Asl[mA0 + ks + t + 4];
            float a3 = Asl[mA1 + ks + t + 4];
            uint32_t ah0,al0,ah1,al1,ah2,al2,ah3,al3;
            split_tf(a0,ah0,al0); split_tf(a1,ah1,al1);
            split_tf(a2,ah2,al2); split_tf(a3,ah3,al3);
            #pragma unroll
            for (int nt = 0; nt < 4; nt++){
                int bn = wn*32 + nt*8 + g;
                uint32_t bh0 = __float_as_uint(Bhl[(ks + t    )*72 + bn]);
                uint32_t bh1 = __float_as_uint(Bhl[(ks + t + 4)*72 + bn]);
                uint32_t bl0 = __float_as_uint(Bll[(ks + t    )*72 + bn]);
                uint32_t bl1 = __float_as_uint(Bll[(ks + t + 4)*72 + bn]);
                mma_tf32(acc[nt], ah0, ah1, ah2, ah3, bh0, bh1);
                mma_tf32(acc[nt], ah0, ah1, ah2, ah3, bl0, bl1);
                mma_tf32(acc[nt], al0, al1, al2, al3, bh0, bh1);
            }
        }
        if (++s >= ST) s -= ST;
    }

    const int r0 = row0 + wm*16 + g;
    const int r1 = r0 + 8;
    #pragma unroll
    for (int nt = 0; nt < 4; nt++){
        int col = col0 + wn*32 + nt*8 + 2*t;
        #pragma unroll
        for (int j = 0; j < 2; j++){
            int c = col + j;
            if (c < N){
                float v0 = acc[nt][j];
                float v1 = acc[nt][2+j];
                if (bias){ float bb = bias[c]; v0 += bb; v1 += bb; }
                if (EPI == 1){ v0 = gelu_f(v0); v1 = gelu_f(v1); }
                if (EPI == 2){
                    v0 += res[(long)r0*ldc + c];
                    v1 += res[(long)r1*ldc + c];
                }
                C[(long)r0*ldc + c] = v0;
                C[(long)r1*ldc + c] = v1;
            }
        }
    }
}

template<int EPI>
__global__ __launch_bounds__(256) void gemm_tc(
    const float* __restrict__ A, int lda,
    const float* __restrict__ Bh, const float* __restrict__ Bl, int ldb,
    float* __restrict__ C, int ldc,
    const float* __restrict__ bias,
    const float* __restrict__ res,
    int M, int N, int K)
{
    gemm_core<EPI>(A, lda, Bh, Bl, ldb, C, ldc, bias, res,
                   M, N, K, blockIdx.y*64, blockIdx.x*64);
}

// Fused QKV: z picks (W, b, out); grid (8,16,3) = 384 blocks
__global__ __launch_bounds__(256) void gemm_qkv(
    const float* __restrict__ n,
    const float* __restrict__ wh, const float* __restrict__ wl, // layer base
    const float* __restrict__ bq, const float* __restrict__ bk, const float* __restrict__ bv,
    float* __restrict__ q, float* __restrict__ k, float* __restrict__ v)
{
    const int z = blockIdx.z;
    // Wq at +0, Wk at +(OFF_WK-OFF_WQ), Wv at +(OFF_WV-OFF_WQ) from layer q-base
    const long dz = (long)z * (OFF_WK - OFF_WQ);
    const float* bias = (z==0) ? bq : (z==1) ? bk : bv;
    float*       C    = (z==0) ? q  : (z==1) ? k  : v;
    gemm_core<0>(n, DM, wh + dz, wl + dz, DM, C, DM, bias, nullptr,
                 SQ, DM, DM, blockIdx.y*64, blockIdx.x*64);
}

// ---------------------------------------------------------------------------
// LayerNorm over D=512. One block (128 threads, 1 float4 each) per row.
// ---------------------------------------------------------------------------
__global__ __launch_bounds__(128) void ln_k(
    const float* __restrict__ x, const float* __restrict__ g,
    const float* __restrict__ b, float* __restrict__ y)
{
    const int row = blockIdx.x, tid = threadIdx.x;
    float4 v = reinterpret_cast<const float4*>(x + (long)row*DM)[tid];
    float s  = v.x+v.y+v.z+v.w;
    float s2 = v.x*v.x+v.y*v.y+v.z*v.z+v.w*v.w;
    #pragma unroll
    for (int o = 16; o; o >>= 1){
        s  += __shfl_xor_sync(0xffffffffu, s,  o);
        s2 += __shfl_xor_sync(0xffffffffu, s2, o);
    }
    __shared__ float sh[8];
    if ((tid & 31) == 0){ sh[tid>>5] = s; sh[4 + (tid>>5)] = s2; }
    __syncthreads();
    s  = sh[0]+sh[1]+sh[2]+sh[3];
    s2 = sh[4]+sh[5]+sh[6]+sh[7];
    const float m = s * (1.f/DM);
    const float rstd = rsqrtf(s2*(1.f/DM) - m*m + 1e-5f);
    float4 gg = reinterpret_cast<const float4*>(g)[tid];
    float4 bb = reinterpret_cast<const float4*>(b)[tid];
    float4 o;
    o.x = (v.x-m)*rstd*gg.x + bb.x;
    o.y = (v.y-m)*rstd*gg.y + bb.y;
    o.z = (v.z-m)*rstd*gg.z + bb.z;
    o.w = (v.w-m)*rstd*gg.w + bb.w;
    reinterpret_cast<float4*>(y + (long)row*DM)[tid] = o;
}

// ---------------------------------------------------------------------------
// Fused flash-style attention with relative position bias (unchanged R10).
// ---------------------------------------------------------------------------
#define AQ_H   0
#define AQ_L   4352
#define AK     8704
#define AE_H   17408
#define AE_L   26112
#define AV     34816
#define AR     44032
#define AREDM  52736
#define AREDS  52864
#define ATT_FLOATS 52992
#define ATT_SMEM  (ATT_FLOATS*4)   // 211968 bytes

__global__ __launch_bounds__(256) void attn_k(
    const float* __restrict__ qg, const float* __restrict__ kg,
    const float* __restrict__ vg,
    const float* __restrict__ erh, const float* __restrict__ erl,
    float* __restrict__ ao)
{
    extern __shared__ float sm[];
    float* QH  = sm + AQ_H;      // [64][68] tf32-hi of Q
    float* QL  = sm + AQ_L;      // [64][68] tf32-lo of Q
    float* KS  = sm + AK;        // [2][64][68] raw fp32 K
    float* EH  = sm + AE_H;      // [128][68] tf32-hi Er band (127 rows used)
    float* EL  = sm + AE_L;      // [128][68] tf32-lo
    float* VS  = sm + AV;        // [2][64][72] raw fp32 V
    float* RS  = sm + AR;        // [64][136]; PH/PL alias after S3
    float* PH  = sm + AR;        // [64][68]
    float* PL  = sm + AR + 4352; // [64][68]
    float* redm = sm + AREDM;    // [2][64]
    float* reds = sm + AREDS;    // [2][64]

    const int s0  = blockIdx.x * 64;
    const int h   = blockIdx.y;
    const int tid = threadIdx.x;
    const int lane = tid & 31, w = tid >> 5;
    const int wm = w & 3, wn = w >> 2;
    const int g = lane >> 2, t = lane & 3;

    // ---- load + pre-split Q tile (once)
    #pragma unroll
    for (int i = 0; i < 4; i++){
        int c = tid + i*256;                  // 0..1023
        int row = c >> 4, q4 = (c & 15) * 4;
        float4 v4 = *(const float4*)(qg + (long)(s0+row)*DM + h*HDIM + q4);
        float xs[4] = {v4.x, v4.y, v4.z, v4.w};
        #pragma unroll
        for (int j = 0; j < 4; j++){
            uint32_t hh, ll; split_tf(xs[j], hh, ll);
            QH[row*68 + q4 + j] = __uint_as_float(hh);
            QL[row*68 + q4 + j] = __uint_as_float(ll);
        }
    }

    auto issue_kv = [&](int t0, int st){
        float* kd = KS + st*4352;
        float* vd = VS + st*4608;
        #pragma unroll
        for (int i = 0; i < 4; i++){
            int c = tid + i*256;
            int row = c >> 4, q4 = (c & 15) * 4;
            cp16((uint32_t)__cvta_generic_to_shared(&kd[row*68 + q4]),
                 kg + (long)(t0+row)*DM + h*HDIM + q4);
            cp16((uint32_t)__cvta_generic_to_shared(&vd[row*72 + q4]),
                 vg + (long)(t0+row)*DM + h*HDIM + q4);
        }
        cp_commit();
    };
    auto issue_e = [&](int t0){
        const int rbase = s0 - t0 + 960;      // Er band start (0..1920)
        #pragma unroll
        for (int i = 0; i < 8; i++){
            int c = tid + i*256;              // need 127*16 = 2032
            if (c < 2032){
                int row = c >> 4, q4 = (c & 15) * 4;
                cp16((uint32_t)__cvta_generic_to_shared(&EH[row*68 + q4]),
                     erh + (long)(rbase+row)*HDIM + q4);
                cp16((uint32_t)__cvta_generic_to_shared(&EL[row*68 + q4]),
                     erl + (long)(rbase+row)*HDIM + q4);
            }
        }
        cp_commit();
    };

    float O[4][4] = {};
    float m0 = -1e30f, m1 = -1e30f, l0 = 0.f, l1 = 0.f;
    const int r0 = wm*16 + g, r1 = r0 + 8;

    issue_kv(0, 0);
    issue_e(0);

    for (int it = 0; it < 16; it++){
        const int st = it & 1;
        asm volatile("cp.async.wait_group 0;\n" ::: "memory");
        __syncthreads();                                       // S1
        if (it < 15) issue_kv((it+1)*64, st ^ 1);

        const float* ksl = KS + st*4352;
        const float* vsl = VS + st*4608;

        // ---- QK + QE mma
        float accS[4][4] = {};
        float accR[2][4][4] = {};
        #pragma unroll
        for (int kk = 0; kk < 64; kk += 8){
            uint32_t ah0 = __float_as_uint(QH[r0*68 + kk + t]);
            uint32_t ah1 = __float_as_uint(QH[r1*68 + kk + t]);
            uint32_t ah2 = __float_as_uint(QH[r0*68 + kk + t + 4]);
            uint32_t ah3 = __float_as_uint(QH[r1*68 + kk + t + 4]);
            uint32_t al0 = __float_as_uint(QL[r0*68 + kk + t]);
            uint32_t al1 = __float_as_uint(QL[r1*68 + kk + t]);
            uint32_t al2 = __float_as_uint(QL[r0*68 + kk + t + 4]);
            uint32_t al3 = __float_as_uint(QL[r1*68 + kk + t + 4]);
            #pragma unroll
            for (int nt = 0; nt < 4; nt++){
                int bn = wn*32 + nt*8 + g;
                float b0 = ksl[bn*68 + kk + t];
                float b1 = ksl[bn*68 + kk + t + 4];
                uint32_t bh0,bl0,bh1,bl1;
                split_tf(b0,bh0,bl0); split_tf(b1,bh1,bl1);
                mma_tf32(accS[nt], ah0,ah1,ah2,ah3, bh0,bh1);
                mma_tf32(accS[nt], ah0,ah1,ah2,ah3, bl0,bl1);
                mma_tf32(accS[nt], al0,al1,al2,al3, bh0,bh1);
            }
            #pragma unroll
            for (int nh = 0; nh < 2; nh++)
            #pragma unroll
            for (int nt = 0; nt < 4; nt++){
                int bn = nh*64 + wn*32 + nt*8 + g;
                uint32_t bh0 = __float_as_uint(EH[bn*68 + kk + t]);
                uint32_t bh1 = __float_as_uint(EH[bn*68 + kk + t + 4]);
                uint32_t bl0 = __float_as_uint(EL[bn*68 + kk + t]);
                uint32_t bl1 = __float_as_uint(EL[bn*68 + kk + t + 4]);
                mma_tf32(accR[nh][nt], ah0,ah1,ah2,ah3, bh0,bh1);
                mma_tf32(accR[nh][nt], ah0,ah1,ah2,ah3, bl0,bl1);
                mma_tf32(accR[nh][nt], al0,al1,al2,al3, bh0,bh1);
            }
        }

        // ---- store R to smem, stride 136
        #pragma unroll
        for (int nh = 0; nh < 2; nh++)
        #pragma unroll
        for (int nt = 0; nt < 4; nt++){
            int u0 = nh*64 + wn*32 + nt*8 + 2*t;
            RS[r0*136 + u0    ] = accR[nh][nt][0];
            RS[r0*136 + u0 + 1] = accR[nh][nt][1];
            RS[r1*136 + u0    ] = accR[nh][nt][2];
            RS[r1*136 + u0 + 1] = accR[nh][nt][3];
        }
        __syncthreads();                                       // S2
        if (it < 15) issue_e((it+1)*64);

        // ---- logits; row max
        float tm0 = -1e30f, tm1 = -1e30f;
        #pragma unroll
        for (int nt = 0; nt < 4; nt++){
            #pragma unroll
            for (int j = 0; j < 2; j++){
                int tj = wn*32 + nt*8 + 2*t + j;
                float x0 = accS[nt][j]   * QK_SCALE + RS[r0*136 + (r0 - tj + 63)];
                float x1 = accS[nt][2+j] * QK_SCALE + RS[r1*136 + (r1 - tj + 63)];
                accS[nt][j]   = x0;
                accS[nt][2+j] = x1;
                tm0 = fmaxf(tm0, x0);
                tm1 = fmaxf(tm1, x1);
            }
        }
        tm0 = fmaxf(tm0, __shfl_xor_sync(0xffffffffu, tm0, 1));
        tm0 = fmaxf(tm0, __shfl_xor_sync(0xffffffffu, tm0, 2));
        tm1 = fmaxf(tm1, __shfl_xor_sync(0xffffffffu, tm1, 1));
        tm1 = fmaxf(tm1, __shfl_xor_sync(0xffffffffu, tm1, 2));
        if (t == 0){ redm[wn*64 + r0] = tm0; redm[wn*64 + r1] = tm1; }
        __syncthreads();                                       // S3

        float M0 = fmaxf(m0, fmaxf(redm[r0], redm[64 + r0]));
        float M1 = fmaxf(m1, fmaxf(redm[r1], redm[64 + r1]));

        // ---- exp, partial sums; write P pre-split (aliases R region)
        float sum0 = 0.f, sum1 = 0.f;
        #pragma unroll
        for (int nt = 0; nt < 4; nt++){
            #pragma unroll
            for (int j = 0; j < 2; j++){
                int tj = wn*32 + nt*8 + 2*t + j;
                float p0 = __expf(accS[nt][j]   - M0);
                float p1 = __expf(accS[nt][2+j] - M1);
                sum0 += p0; sum1 += p1;
                uint32_t hh, ll;
                split_tf(p0, hh, ll);
                PH[r0*68 + tj] = __uint_as_float(hh);
                PL[r0*68 + tj] = __uint_as_float(ll);
                split_tf(p1, hh, ll);
                PH[r1*68 + tj] = __uint_as_float(hh);
                PL[r1*68 + tj] = __uint_as_float(ll);
            }
        }
        sum0 += __shfl_xor_sync(0xffffffffu, sum0, 1);
        sum0 += __shfl_xor_sync(0xffffffffu, sum0, 2);
        sum1 += __shfl_xor_sync(0xffffffffu, sum1, 1);
        sum1 += __shfl_xor_sync(0xffffffffu, sum1, 2);
        if (t == 0){ reds[wn*64 + r0] = sum0; reds[wn*64 + r1] = sum1; }

        float f0 = __expf(m0 - M0), f1 = __expf(m1 - M1);
        #pragma unroll
        for (int nt = 0; nt < 4; nt++){
            O[nt][0] *= f0; O[nt][1] *= f0;
            O[nt][2] *= f1; O[nt][3] *= f1;
        }
        __syncthreads();                                       // S4

        l0 = l0*f0 + reds[r0] + reds[64 + r0];
        l1 = l1*f1 + reds[r1] + reds[64 + r1];
        m0 = M0; m1 = M1;

        // ---- O += P @ V
        #pragma unroll
        for (int kk = 0; kk < 64; kk += 8){
            uint32_t ah0 = __float_as_uint(PH[r0*68 + kk + t]);
            uint32_t ah1 = __float_as_uint(PH[r1*68 + kk + t]);
            uint32_t ah2 = __float_as_uint(PH[r0*68 + kk + t + 4]);
            uint32_t ah3 = __float_as_uint(PH[r1*68 + kk + t + 4]);
            uint32_t al0 = __float_as_uint(PL[r0*68 + kk + t]);
            uint32_t al1 = __float_as_uint(PL[r1*68 + kk + t]);
            uint32_t al2 = __float_as_uint(PL[r0*68 + kk + t + 4]);
            uint32_t al3 = __float_as_uint(PL[r1*68 + kk + t + 4]);
            #pragma unroll
            for (int nt = 0; nt < 4; nt++){
                int bn = wn*32 + nt*8 + g;
                float b0 = vsl[(kk + t    )*72 + bn];
                float b1 = vsl[(kk + t + 4)*72 + bn];
                uint32_t bh0,bl0,bh1,bl1;
                split_tf(b0,bh0,bl0); split_tf(b1,bh1,bl1);
                mma_tf32(O[nt], ah0,ah1,ah2,ah3, bh0,bh1);
                mma_tf32(O[nt], ah0,ah1,ah2,ah3, bl0,bl1);
                mma_tf32(O[nt], al0,al1,al2,al3, bh0,bh1);
            }
        }
    }

    // ---- epilogue
    const float il0 = 1.f / l0, il1 = 1.f / l1;
    const int gr0 = s0 + r0, gr1 = s0 + r1;
    #pragma unroll
    for (int nt = 0; nt < 4; nt++){
        #pragma unroll
        for (int j = 0; j < 2; j++){
            int dc = h*HDIM + wn*32 + nt*8 + 2*t + j;
            ao[(long)gr0*DM + dc] = O[nt][j]   * il0;
            ao[(long)gr1*DM + dc] = O[nt][2+j] * il1;
        }
    }
}

// ---------------------------------------------------------------------------
// Host orchestration
// ---------------------------------------------------------------------------
extern "C" void kernel_launch(void* const* d_in, const int* in_sizes, int n_in,
                              void* d_out, int out_size)
{
    const float* x     = (const float*)d_in[0];
    const float* emb_W = (const float*)d_in[1];
    const float* emb_b = (const float*)d_in[2];
    const float* Wq    = (const float*)d_in[3];
    const float* bq    = (const float*)d_in[4];
    const float* Wk    = (const float*)d_in[5];
    const float* bk    = (const float*)d_in[6];
    const float* Wv    = (const float*)d_in[7];
    const float* bv    = (const float*)d_in[8];
    const float* Wo    = (const float*)d_in[9];
    const float* bo    = (const float*)d_in[10];
    const float* Er    = (const float*)d_in[11];
    const float* ln1g  = (const float*)d_in[12];
    const float* ln1b  = (const float*)d_in[13];
    const float* W1    = (const float*)d_in[14];
    const float* b1    = (const float*)d_in[15];
    const float* W2    = (const float*)d_in[16];
    const float* b2    = (const float*)d_in[17];
    const float* ln2g  = (const float*)d_in[18];
    const float* ln2b  = (const float*)d_in[19];
    const float* lnfg  = (const float*)d_in[20];
    const float* lnfb  = (const float*)d_in[21];
    const float* Wi    = (const float*)d_in[22];
    const float* bi    = (const float*)d_in[23];
    const float* Wf    = (const float*)d_in[24];
    const float* bf    = (const float*)d_in[25];
    float* out = (float*)d_out;

    float *h, *n, *q, *k, *v, *ao, *f1, *fi, *wh, *wl, *erh, *erl;
    cudaGetSymbolAddress((void**)&h,  g_h);
    cudaGetSymbolAddress((void**)&n,  g_n);
    cudaGetSymbolAddress((void**)&q,  g_q);
    cudaGetSymbolAddress((void**)&k,  g_k);
    cudaGetSymbolAddress((void**)&v,  g_v);
    cudaGetSymbolAddress((void**)&ao, g_ao);
    cudaGetSymbolAddress((void**)&f1, g_f1);
    cudaGetSymbolAddress((void**)&fi, g_fi);
    cudaGetSymbolAddress((void**)&wh, g_wh);
    cudaGetSymbolAddress((void**)&wl, g_wl);
    cudaGetSymbolAddress((void**)&erh, g_erh);
    cudaGetSymbolAddress((void**)&erl, g_erl);

    cudaFuncSetAttribute(attn_k, cudaFuncAttributeMaxDynamicSharedMemorySize, ATT_SMEM);

    // ---- one-time (per replay) weight pre-split
    auto wsplit = [&](const float* src, long off, int nfl){
        int n4 = nfl >> 2;
        wsplit_k<<<(n4 + 255)/256, 256>>>((const float4*)src,
                                          (float4*)(wh + off), (float4*)(wl + off), n4);
    };
    wsplit(emb_W, OFF_EMB, 65536);
    wsplit(Wq,    OFF_WQ,  NLAY*DM*DM);
    wsplit(Wk,    OFF_WK,  NLAY*DM*DM);
    wsplit(Wv,    OFF_WV,  NLAY*DM*DM);
    wsplit(Wo,    OFF_WO,  NLAY*DM*DM);
    wsplit(W1,    OFF_W1,  NLAY*DM*2048);
    wsplit(W2,    OFF_W2,  NLAY*2048*DM);
    wsplit(Wi,    OFF_WI,  DM*1024);
    wsplit(Wf,    OFF_WF,  1024*390);
    {   // all layers of Er at once
        int n4 = (NLAY*2047*HDIM) >> 2;
        wsplit_k<<<(n4 + 255)/256, 256>>>((const float4*)Er,
                                          (float4*)erh, (float4*)erl, n4);
    }

    // embed: h = x @ emb_W + emb_b
    gemm_tc<0><<<dim3(8,16), 256>>>(x,128, wh+OFF_EMB, wl+OFF_EMB,512,
                                    h,512, emb_b, nullptr, SQ, DM, 128);

    for (int l = 0; l < NLAY; l++) {
        const long lw  = (long)l*DM*DM;
        const long lw1 = (long)l*DM*2048;

        ln_k<<<SQ,128>>>(h, ln1g + l*DM, ln1b + l*DM, n);

        gemm_qkv<<<dim3(8,16,3),256>>>(n, wh+OFF_WQ+lw, wl+OFF_WQ+lw,
                                       bq + l*DM, bk + l*DM, bv + l*DM, q, k, v);

        attn_k<<<dim3(16,NH),256,ATT_SMEM>>>(q, k, v,
                                             erh + (long)l*2047*HDIM,
                                             erl + (long)l*2047*HDIM, ao);

        gemm_tc<2><<<dim3(8,16),256>>>(ao,DM, wh+OFF_WO+lw, wl+OFF_WO+lw,DM,
                                       h,DM, bo + l*DM, h, SQ, DM, DM);

        ln_k<<<SQ,128>>>(h, ln2g + l*DM, ln2b + l*DM, n);

        gemm_tc<1><<<dim3(32,16),256>>>(n,DM, wh+OFF_W1+lw1, wl+OFF_W1+lw1,2048,
                                        f1,2048, b1 + l*2048, nullptr, SQ, 2048, DM);

        gemm_tc<2><<<dim3(8,16),256>>>(f1,2048, wh+OFF_W2+lw1, wl+OFF_W2+lw1,DM,
                                       h,DM, b2 + l*DM, h, SQ, DM, 2048);
    }

    ln_k<<<SQ,128>>>(h, lnfg, lnfb, n);
    gemm_tc<1><<<dim3(16,16),256>>>(n,DM, wh+OFF_WI, wl+OFF_WI,1024,
                                    fi,1024, bi, nullptr, SQ, 1024, DM);
    gemm_tc<0><<<dim3(7,16),256>>>(fi,1024, wh+OFF_WF, wl+OFF_WF,390,
                                   out,390, bf, nullptr, SQ, 390, 1024);
}